// round 1
// baseline (speedup 1.0000x reference)
#include <cuda_runtime.h>
#include <math.h>

// Sizes fixed by the problem
#define BG 2048           // per-group batch
#define BT 4096           // total batch

// ---------------- scratch (device globals; no allocation allowed) ----------
__device__ float g_zt[2 * BG * 64];     // relu(zw @ lw.T + lb)
__device__ float g_s[2 * BG];           // attention scores
__device__ float g_m[2];                // max of s per group
__device__ float g_Ssum[2];             // sum exp(s-m) per group
__device__ float g_T[2 * 64];           // sum exp(s-m) * zt per group
__device__ float g_pred[BT * 128];      // pred rows
__device__ float g_pm[BT * 32];         // per-row per-jtile max
__device__ float g_ps[BT * 32];         // per-row per-jtile sumexp
__device__ float g_diag[BT];            // total[i][i]

// ---------------------------------------------------------------------------
// K1: zt = relu(zw @ lw.T + lb)  and  s = tanh(zt@a1.T+a1b)@a2 + a2b
// grid (64, 2), block 256.  32 rows / block.
// ---------------------------------------------------------------------------
__global__ void k1_zt_s(const float* __restrict__ zw0, const float* __restrict__ zw1,
                        const float* __restrict__ l0w, const float* __restrict__ l0b,
                        const float* __restrict__ l1w, const float* __restrict__ l1b,
                        const float* __restrict__ a01w, const float* __restrict__ a01b,
                        const float* __restrict__ a02w, const float* __restrict__ a02b,
                        const float* __restrict__ a11w, const float* __restrict__ a11b,
                        const float* __restrict__ a12w, const float* __restrict__ a12b)
{
    __shared__ float sLW[64 * 129];   // lin weight, padded
    __shared__ float sZT[32 * 65];    // zt rows, padded
    __shared__ float sA2[32];
    __shared__ float sLB[64];
    __shared__ float sA1B[32];

    const int g = blockIdx.y;
    const float* zw  = g ? zw1  : zw0;
    const float* lw  = g ? l1w  : l0w;
    const float* lb  = g ? l1b  : l0b;
    const float* a1w = g ? a11w : a01w;
    const float* a1b = g ? a11b : a01b;
    const float* a2w = g ? a12w : a02w;
    const float* a2b = g ? a12b : a02b;

    const int t = threadIdx.x;
    const int r0 = blockIdx.x * 32;

    for (int i = t; i < 64 * 128; i += 256)
        sLW[(i >> 7) * 129 + (i & 127)] = lw[i];
    if (t < 64) sLB[t] = lb[t];
    if (t < 32) { sA2[t] = a2w[t]; sA1B[t] = a1b[t]; }
    __syncthreads();

    // each thread: row r = t/8, cols cg + 8*i (interleaved -> conflict free)
    const int r  = t >> 3;
    const int cg = t & 7;
    float acc[8];
#pragma unroll
    for (int i = 0; i < 8; i++) acc[i] = sLB[cg + 8 * i];

    const float* zrow = zw + (size_t)(r0 + r) * 128;
#pragma unroll 4
    for (int k = 0; k < 128; k++) {
        float a = __ldg(zrow + k);
#pragma unroll
        for (int i = 0; i < 8; i++) acc[i] += a * sLW[(cg + 8 * i) * 129 + k];
    }
#pragma unroll
    for (int i = 0; i < 8; i++) {
        float v = fmaxf(acc[i], 0.0f);
        sZT[r * 65 + cg + 8 * i] = v;
        g_zt[(size_t)(g * BG + r0 + r) * 64 + cg + 8 * i] = v;
    }
    __syncthreads();

    // s per row: warp w handles rows 4w..4w+3
    const int w = t >> 5, lane = t & 31;
    for (int rr = 0; rr < 4; rr++) {
        const int row = w * 4 + rr;
        float d = sA1B[lane];
#pragma unroll 4
        for (int k = 0; k < 64; k++)
            d += sZT[row * 65 + k] * __ldg(a1w + lane * 64 + k);
        float v = tanhf(d) * sA2[lane];
#pragma unroll
        for (int off = 16; off; off >>= 1)
            v += __shfl_down_sync(0xffffffffu, v, off);
        if (lane == 0) g_s[g * BG + r0 + row] = v + __ldg(a2b);
    }
}

// ---------------------------------------------------------------------------
// K2a: per-group max of s.  grid 2, block 256.
// ---------------------------------------------------------------------------
__global__ void k2a_max()
{
    __shared__ float red[256];
    const int g = blockIdx.x, t = threadIdx.x;
    float mx = -1e30f;
    for (int j = t; j < BG; j += 256) mx = fmaxf(mx, g_s[g * BG + j]);
    red[t] = mx; __syncthreads();
    for (int off = 128; off; off >>= 1) {
        if (t < off) red[t] = fmaxf(red[t], red[t + off]);
        __syncthreads();
    }
    if (t == 0) g_m[g] = red[0];
}

// ---------------------------------------------------------------------------
// K2b: T[c] = sum_j e^{s_j-m} zt[j][c]  (c<64),  S = sum_j e^{s_j-m} (c==64)
// grid (65, 2), block 256. Deterministic fixed-order reduction.
// ---------------------------------------------------------------------------
__global__ void k2b_sums()
{
    __shared__ float red[256];
    const int g = blockIdx.y, c = blockIdx.x, t = threadIdx.x;
    const float m = g_m[g];
    float p = 0.0f;
    if (c < 64) {
        for (int j = t; j < BG; j += 256)
            p += expf(g_s[g * BG + j] - m) * g_zt[(size_t)(g * BG + j) * 64 + c];
    } else {
        for (int j = t; j < BG; j += 256)
            p += expf(g_s[g * BG + j] - m);
    }
    red[t] = p; __syncthreads();
    for (int off = 128; off; off >>= 1) {
        if (t < off) red[t] += red[t + off];
        __syncthreads();
    }
    if (t == 0) {
        if (c < 64) g_T[g * 64 + c] = red[0];
        else        g_Ssum[g] = red[0];
    }
}

// ---------------------------------------------------------------------------
// K3: pred = pooled @ Ww.T + Wwb + c @ Wk.T + Wkb
// pooled_i = (T - e_i * zt_i) / (S - e_i),  e_i = exp(s_i - m)
// grid 128, block 256; 32 rows/block. Two phases to stay under 48KB smem.
// ---------------------------------------------------------------------------
__global__ void k3_pred(const float* __restrict__ cin,
                        const float* __restrict__ Wkw, const float* __restrict__ Wkb,
                        const float* __restrict__ Ww0w, const float* __restrict__ Ww0b,
                        const float* __restrict__ Ww1w, const float* __restrict__ Ww1b)
{
    __shared__ float sW[128 * 65];  // one 128x64 weight (padded)
    __shared__ float sU[32 * 65];   // 32 input rows of 64 (padded)
    __shared__ float sE[32], sI[32], sB[128];

    const int t = threadIdx.x;
    const int row0 = blockIdx.x * 32;
    const int g = row0 >= BG;
    const int lr0 = row0 - g * BG;
    const float* Www = g ? Ww1w : Ww0w;
    const float* Wwb = g ? Ww1b : Ww0b;

    if (t < 128) sB[t] = Wwb[t] + Wkb[t];
    if (t < 32) {
        float e = expf(g_s[g * BG + lr0 + t] - g_m[g]);
        sE[t] = e;
        sI[t] = 1.0f / (g_Ssum[g] - e);
    }
    // phase A weight: Ww
    for (int i = t; i < 128 * 64; i += 256)
        sW[(i >> 6) * 65 + (i & 63)] = Www[i];
    __syncthreads();
    // phase A input: pooled rows (needs sE/sI)
    for (int i = t; i < 32 * 64; i += 256) {
        int r = i >> 6, k = i & 63;
        sU[r * 65 + k] = (g_T[g * 64 + k] -
                          sE[r] * g_zt[(size_t)(g * BG + lr0 + r) * 64 + k]) * sI[r];
    }
    __syncthreads();

    const int r = t >> 3, cg = t & 7;
    float acc[16];
#pragma unroll
    for (int i = 0; i < 16; i++) acc[i] = sB[cg + 8 * i];
#pragma unroll 4
    for (int k = 0; k < 64; k++) {
        float a = sU[r * 65 + k];
#pragma unroll
        for (int i = 0; i < 16; i++) acc[i] += a * sW[(cg + 8 * i) * 65 + k];
    }
    __syncthreads();

    // phase B: Wk and c rows
    for (int i = t; i < 128 * 64; i += 256)
        sW[(i >> 6) * 65 + (i & 63)] = Wkw[i];
    for (int i = t; i < 32 * 64; i += 256) {
        int rr = i >> 6, k = i & 63;
        sU[rr * 65 + k] = cin[(size_t)(row0 + rr) * 64 + k];
    }
    __syncthreads();
#pragma unroll 4
    for (int k = 0; k < 64; k++) {
        float a = sU[r * 65 + k];
#pragma unroll
        for (int i = 0; i < 16; i++) acc[i] += a * sW[(cg + 8 * i) * 65 + k];
    }
#pragma unroll
    for (int i = 0; i < 16; i++)
        g_pred[(size_t)(row0 + r) * 128 + cg + 8 * i] = acc[i];
}

// ---------------------------------------------------------------------------
// K4: fused  total = zw @ pred.T  +  per-row (max, sumexp) over this 128-col
// tile + diagonal extraction.  grid (32, 32), block 256, 128x128 tile,
// 8x8 register blocking, TK=32 k-chunks, k-major smem.
// ---------------------------------------------------------------------------
__global__ __launch_bounds__(256, 2)
void k4_gemm_lse(const float* __restrict__ zw0, const float* __restrict__ zw1)
{
    __shared__ float sm[2 * 32 * 132];     // sA | sB ; reused for epilogue
    float* sA = sm;
    float* sB = sm + 32 * 132;

    const int it = blockIdx.y, jt = blockIdx.x;
    const int row0 = it * 128, col0 = jt * 128;
    const float* Ar = (row0 < BG) ? zw0 + (size_t)row0 * 128
                                  : zw1 + (size_t)(row0 - BG) * 128;
    const float* Br = g_pred + (size_t)col0 * 128;

    const int t = threadIdx.x;
    const int ty = t >> 4, tx = t & 15;

    float acc[8][8];
#pragma unroll
    for (int i = 0; i < 8; i++)
#pragma unroll
        for (int j = 0; j < 8; j++) acc[i][j] = 0.0f;

#pragma unroll 1
    for (int kt = 0; kt < 4; kt++) {
        // load 128x32 chunks of A and B (k-major into smem)
#pragma unroll
        for (int i = 0; i < 4; i++) {
            int idx = t + 256 * i;            // 0..1023 float4s
            int r = idx >> 3;
            int kk = (idx & 7) << 2;
            float4 va = *(const float4*)(Ar + (size_t)r * 128 + kt * 32 + kk);
            sA[(kk + 0) * 132 + r] = va.x;
            sA[(kk + 1) * 132 + r] = va.y;
            sA[(kk + 2) * 132 + r] = va.z;
            sA[(kk + 3) * 132 + r] = va.w;
            float4 vb = *(const float4*)(Br + (size_t)r * 128 + kt * 32 + kk);
            sB[(kk + 0) * 132 + r] = vb.x;
            sB[(kk + 1) * 132 + r] = vb.y;
            sB[(kk + 2) * 132 + r] = vb.z;
            sB[(kk + 3) * 132 + r] = vb.w;
        }
        __syncthreads();
#pragma unroll 4
        for (int k = 0; k < 32; k++) {
            float4 a0 = *(const float4*)&sA[k * 132 + ty * 8];
            float4 a1 = *(const float4*)&sA[k * 132 + ty * 8 + 4];
            float4 b0 = *(const float4*)&sB[k * 132 + tx * 8];
            float4 b1 = *(const float4*)&sB[k * 132 + tx * 8 + 4];
            float av[8] = {a0.x, a0.y, a0.z, a0.w, a1.x, a1.y, a1.z, a1.w};
            float bv[8] = {b0.x, b0.y, b0.z, b0.w, b1.x, b1.y, b1.z, b1.w};
#pragma unroll
            for (int i = 0; i < 8; i++)
#pragma unroll
                for (int j = 0; j < 8; j++) acc[i][j] += av[i] * bv[j];
        }
        __syncthreads();
    }

    // diagonal (row==col globally)
    if (it == jt && ty == tx) {
#pragma unroll
        for (int i = 0; i < 8; i++)
            g_diag[row0 + ty * 8 + i] = acc[i][i];
    }

    // epilogue: per-row (max, sumexp) over this 128-col tile
    float2* red = (float2*)sm;                 // 128 rows x 16 partials
#pragma unroll
    for (int i = 0; i < 8; i++) {
        float mx = acc[i][0];
#pragma unroll
        for (int j = 1; j < 8; j++) mx = fmaxf(mx, acc[i][j]);
        float ss = 0.0f;
#pragma unroll
        for (int j = 0; j < 8; j++) ss += expf(acc[i][j] - mx);
        red[(ty * 8 + i) * 16 + tx] = make_float2(mx, ss);
    }
    __syncthreads();
    if (t < 128) {
        float M = -1e30f, S = 0.0f;
#pragma unroll
        for (int p = 0; p < 16; p++) {
            float2 v = red[t * 16 + p];
            if (v.x > M) { S = S * expf(M - v.x) + v.y; M = v.x; }
            else         { S += v.y * expf(v.x - M); }
        }
        g_pm[(size_t)(row0 + t) * 32 + jt] = M;
        g_ps[(size_t)(row0 + t) * 32 + jt] = S;
    }
}

// ---------------------------------------------------------------------------
// K5: combine partials -> lse per row; nce = sum(lse - diag) / 4096.
// single block, fixed-order reductions (deterministic).
// ---------------------------------------------------------------------------
__global__ void k5_final(float* __restrict__ out)
{
    __shared__ float red[256];
    const int t = threadIdx.x;
    float a = 0.0f;
    for (int rr = 0; rr < 16; rr++) {
        const int row = rr * 256 + t;
        float M = -1e30f, S = 0.0f;
#pragma unroll 4
        for (int p = 0; p < 32; p++) {
            float m = g_pm[(size_t)row * 32 + p];
            float s = g_ps[(size_t)row * 32 + p];
            if (m > M) { S = S * expf(M - m) + s; M = m; }
            else       { S += s * expf(m - M); }
        }
        a += (M + logf(S)) - g_diag[row];
    }
    red[t] = a; __syncthreads();
    for (int off = 128; off; off >>= 1) {
        if (t < off) red[t] += red[t + off];
        __syncthreads();
    }
    if (t == 0) out[0] = red[0] / (float)BT;
}

// ---------------------------------------------------------------------------
extern "C" void kernel_launch(void* const* d_in, const int* in_sizes, int n_in,
                              void* d_out, int out_size)
{
    const float* zw0  = (const float*)d_in[0];
    const float* zw1  = (const float*)d_in[1];
    const float* cin  = (const float*)d_in[2];
    const float* Wkw  = (const float*)d_in[3];
    const float* Wkb  = (const float*)d_in[4];
    const float* Ww0w = (const float*)d_in[5];
    const float* Ww0b = (const float*)d_in[6];
    const float* Ww1w = (const float*)d_in[7];
    const float* Ww1b = (const float*)d_in[8];
    const float* l0w  = (const float*)d_in[9];
    const float* l0b  = (const float*)d_in[10];
    const float* l1w  = (const float*)d_in[11];
    const float* l1b  = (const float*)d_in[12];
    const float* a01w = (const float*)d_in[13];
    const float* a01b = (const float*)d_in[14];
    const float* a02w = (const float*)d_in[15];
    const float* a02b = (const float*)d_in[16];
    const float* a11w = (const float*)d_in[17];
    const float* a11b = (const float*)d_in[18];
    const float* a12w = (const float*)d_in[19];
    const float* a12b = (const float*)d_in[20];

    k1_zt_s<<<dim3(64, 2), 256>>>(zw0, zw1, l0w, l0b, l1w, l1b,
                                  a01w, a01b, a02w, a02b,
                                  a11w, a11b, a12w, a12b);
    k2a_max<<<2, 256>>>();
    k2b_sums<<<dim3(65, 2), 256>>>();
    k3_pred<<<128, 256>>>(cin, Wkw, Wkb, Ww0w, Ww0b, Ww1w, Ww1b);
    k4_gemm_lse<<<dim3(32, 32), 256>>>(zw0, zw1);
    k5_final<<<1, 256>>>((float*)d_out);
}

// round 7
// speedup vs baseline: 2.3495x; 2.3495x over previous
#include <cuda_runtime.h>
#include <cuda_bf16.h>
#include <math.h>
#include <stdint.h>

#define BG 2048
#define BT 4096

// Does this compilation pass support tcgen05 (arch-accelerated 'a' features)?
#if defined(__CUDA_ARCH_FEAT_SM103_ALL) || defined(__CUDA_ARCH_FEAT_SM100_ALL) || defined(__CUDA_ARCH_FEAT_SM101_ALL)
#define K4_TC 1
#else
#define K4_TC 0
#endif

// ---------------- scratch ----------------
__device__ float g_zt[2 * BG * 64];
__device__ float g_s[2 * BG];
__device__ float g_m[2];
__device__ float g_Ssum[2];
__device__ float g_T[2 * 64];
__device__ float g_pred[BT * 128];
__device__ float g_pm[BT * 32];
__device__ float g_ps[BT * 32];
__device__ float g_diag[BT];
__device__ float g_part[32];

// ---------------- PTX helpers ----------------
__device__ __forceinline__ uint32_t smem_u32(const void* p) {
    uint32_t a;
    asm("{ .reg .u64 t; cvta.to.shared.u64 t, %1; cvt.u32.u64 %0, t; }" : "=r"(a) : "l"(p));
    return a;
}
__device__ __forceinline__ bool elect_one() {
    uint32_t p;
    asm volatile("{\n\t.reg .pred p;\n\telect.sync _|p, 0xFFFFFFFF;\n\tselp.b32 %0, 1, 0, p;\n\t}" : "=r"(p));
    return p != 0;
}
#define MBAR_INIT(a, c) asm volatile("mbarrier.init.shared.b64 [%0], %1;" :: "r"(a), "r"((uint32_t)(c)) : "memory")
#define MBAR_INVAL(a)   asm volatile("mbarrier.inval.shared.b64 [%0];" :: "r"(a) : "memory")
#define MBAR_WAIT(mb, ph) do { \
    uint32_t _m = (uint32_t)(mb), _p = (uint32_t)(ph), _d; \
    asm volatile("{\n\t.reg .pred p;\n\tmbarrier.try_wait.parity.acquire.cta.shared::cta.b64 p, [%1], %2;\n\tselp.b32 %0, 1, 0, p;\n\t}" \
        : "=r"(_d) : "r"(_m), "r"(_p) : "memory"); \
    if (!_d) { \
        asm volatile("{\n\t.reg .pred P1;\n\tWL_%=:\n\tmbarrier.try_wait.parity.acquire.cta.shared::cta.b64 P1, [%0], %1, 0x989680;\n\t@P1 bra.uni WD_%=;\n\tbra.uni WL_%=;\n\tWD_%=:\n\t}" \
            :: "r"(_m), "r"(_p) : "memory"); \
    } } while (0)

#if K4_TC
#define TC_ALLOC(a, n)  asm volatile("tcgen05.alloc.cta_group::1.sync.aligned.shared::cta.b32 [%0], %1;" :: "r"(a), "r"((uint32_t)(n)) : "memory")
#define TC_RELINQ()     asm volatile("tcgen05.relinquish_alloc_permit.cta_group::1.sync.aligned;")
#define TC_DEALLOC(t, n) asm volatile("tcgen05.dealloc.cta_group::1.sync.aligned.b32 %0, %1;" :: "r"(t), "r"((uint32_t)(n)))
#define TC_COMMIT(mb)   asm volatile("tcgen05.commit.cta_group::1.mbarrier::arrive::one.shared::cluster.b64 [%0];" :: "r"(mb) : "memory")
#define TC_FENCE_AFTER() asm volatile("tcgen05.fence::after_thread_sync;" ::: "memory")
#define TC_WAIT_LD()    asm volatile("tcgen05.wait::ld.sync.aligned;" ::: "memory")
#define FENCE_ASYNC()   asm volatile("fence.proxy.async.shared::cta;" ::: "memory")

#define LDTM_X32(r, ta) \
    asm volatile("tcgen05.ld.sync.aligned.32x32b.x32.b32 " \
        "{%0, %1, %2, %3, %4, %5, %6, %7, %8, %9, %10, %11, %12, %13, %14, %15, " \
        " %16, %17, %18, %19, %20, %21, %22, %23, %24, %25, %26, %27, %28, %29, %30, %31}, [%32];" \
        : "=r"((r)[0]),  "=r"((r)[1]),  "=r"((r)[2]),  "=r"((r)[3]), \
          "=r"((r)[4]),  "=r"((r)[5]),  "=r"((r)[6]),  "=r"((r)[7]), \
          "=r"((r)[8]),  "=r"((r)[9]),  "=r"((r)[10]), "=r"((r)[11]), \
          "=r"((r)[12]), "=r"((r)[13]), "=r"((r)[14]), "=r"((r)[15]), \
          "=r"((r)[16]), "=r"((r)[17]), "=r"((r)[18]), "=r"((r)[19]), \
          "=r"((r)[20]), "=r"((r)[21]), "=r"((r)[22]), "=r"((r)[23]), \
          "=r"((r)[24]), "=r"((r)[25]), "=r"((r)[26]), "=r"((r)[27]), \
          "=r"((r)[28]), "=r"((r)[29]), "=r"((r)[30]), "=r"((r)[31]) \
        : "r"(ta))

__device__ __forceinline__ uint64_t make_desc(uint32_t addr) {
    // SW128, Blackwell v1, SBO=64 (1024B), LBO=1 (16B)
    const uint64_t base = (2ull << 61) | (1ull << 46) | (64ull << 32) | (1ull << 16);
    return base | ((uint64_t)(addr >> 4) & 0x3FFF);
}
// kind::f16, dtype=F32, a=b=BF16, N=128, M=128 (encoding family of 0x8080490)
#define IDESC_K4 ((1u << 4) | (1u << 7) | (1u << 10) | ((128u / 8) << 17) | ((128u / 16) << 24))

__device__ __forceinline__ void mma_ss(uint32_t d, uint64_t ad, uint64_t bd, bool en) {
    uint32_t e = en ? 1u : 0u;
    asm volatile(
        "{\n\t.reg .pred p;\n\tsetp.ne.u32 p, %4, 0;\n\t"
        "tcgen05.mma.cta_group::1.kind::f16 [%0], %1, %2, %3, {%5, %5, %5, %5}, p;\n\t}"
        :: "r"(d), "l"(ad), "l"(bd), "r"(IDESC_K4), "r"(e), "r"(0u) : "memory");
}

__device__ __forceinline__ void cvt4(float4 v, uint2& hi, uint2& lo) {
    __nv_bfloat162 h01 = __floats2bfloat162_rn(v.x, v.y);
    __nv_bfloat162 h23 = __floats2bfloat162_rn(v.z, v.w);
    float2 f01 = __bfloat1622float2(h01);
    float2 f23 = __bfloat1622float2(h23);
    __nv_bfloat162 l01 = __floats2bfloat162_rn(v.x - f01.x, v.y - f01.y);
    __nv_bfloat162 l23 = __floats2bfloat162_rn(v.z - f23.x, v.w - f23.y);
    hi.x = *reinterpret_cast<uint32_t*>(&h01);
    hi.y = *reinterpret_cast<uint32_t*>(&h23);
    lo.x = *reinterpret_cast<uint32_t*>(&l01);
    lo.y = *reinterpret_cast<uint32_t*>(&l23);
}
__device__ __forceinline__ uint32_t swz(uint32_t b) { return b ^ ((b >> 3) & 0x70); }
#endif  // K4_TC

// ---------------------------------------------------------------------------
// K1: zt = relu(zw @ lw.T + lb); s = tanh(zt@a1.T+a1b)@a2 + a2b
// grid (64, 2), block 256.
// ---------------------------------------------------------------------------
__global__ __launch_bounds__(256) void k1_zt_s(
    const float* __restrict__ zw0, const float* __restrict__ zw1,
    const float* __restrict__ l0w, const float* __restrict__ l0b,
    const float* __restrict__ l1w, const float* __restrict__ l1b,
    const float* __restrict__ a01w, const float* __restrict__ a01b,
    const float* __restrict__ a02w, const float* __restrict__ a02b,
    const float* __restrict__ a11w, const float* __restrict__ a11b,
    const float* __restrict__ a12w, const float* __restrict__ a12b)
{
    __shared__ float sLW[64 * 132];
    __shared__ float sZT[32 * 65];

    const int g = blockIdx.y;
    const float* zw  = g ? zw1  : zw0;
    const float* lw  = g ? l1w  : l0w;
    const float* lb  = g ? l1b  : l0b;
    const float* a1w = g ? a11w : a01w;
    const float* a1b = g ? a11b : a01b;
    const float* a2w = g ? a12w : a02w;
    const float* a2b = g ? a12b : a02b;

    const int t = threadIdx.x;
    const int r0 = blockIdx.x * 32;

    {
        const float4* src = (const float4*)lw;
#pragma unroll
        for (int i = 0; i < 8; i++) {
            int idx = t + 256 * i;
            int o = idx >> 5, q = idx & 31;
            *(float4*)&sLW[o * 132 + q * 4] = __ldg(src + idx);
        }
    }
    __syncthreads();

    const int r = t >> 3, cg = t & 7;
    float acc[8];
#pragma unroll
    for (int i = 0; i < 8; i++) acc[i] = __ldg(lb + cg + 8 * i);

    const float4* zp = (const float4*)(zw + (size_t)(r0 + r) * 128);
#pragma unroll 8
    for (int q = 0; q < 32; q++) {
        float4 a = __ldg(zp + q);
#pragma unroll
        for (int i = 0; i < 8; i++) {
            float4 w = *(const float4*)&sLW[(cg + 8 * i) * 132 + q * 4];
            acc[i] += a.x * w.x + a.y * w.y + a.z * w.z + a.w * w.w;
        }
    }
#pragma unroll
    for (int i = 0; i < 8; i++) {
        float v = fmaxf(acc[i], 0.0f);
        sZT[r * 65 + cg + 8 * i] = v;
        g_zt[(size_t)(g * BG + r0 + r) * 64 + cg + 8 * i] = v;
    }
    __syncthreads();

    const int w = t >> 5, lane = t & 31;
    const float a2v  = __ldg(a2w + lane);
    const float a1bv = __ldg(a1b + lane);
    const float a2bv = __ldg(a2b);
    for (int rr = 0; rr < 4; rr++) {
        const int row = w * 4 + rr;
        float d = a1bv;
#pragma unroll 8
        for (int k = 0; k < 64; k++)
            d += sZT[row * 65 + k] * __ldg(a1w + lane * 64 + k);
        float v = tanhf(d) * a2v;
#pragma unroll
        for (int off = 16; off; off >>= 1) v += __shfl_down_sync(0xffffffffu, v, off);
        if (lane == 0) g_s[g * BG + r0 + row] = v + a2bv;
    }
}

// ---------------------------------------------------------------------------
// K2: per group: m = max(s); e = exp(s-m); T[c] = sum e*zt[:,c]; Ssum = sum e.
// grid 2, block 1024. Fixed-order reductions, coalesced zt reads.
// ---------------------------------------------------------------------------
__global__ __launch_bounds__(1024) void k2_pool()
{
    __shared__ float sE[2048];
    __shared__ float red[1024];
    __shared__ float sP[16 * 68];

    const int g = blockIdx.x, t = threadIdx.x;

    // group max
    float a = fmaxf(g_s[g * BG + t], g_s[g * BG + 1024 + t]);
    red[t] = a; __syncthreads();
    for (int off = 512; off; off >>= 1) {
        if (t < off) red[t] = fmaxf(red[t], red[t + off]);
        __syncthreads();
    }
    const float m = red[0];
    if (t == 0) g_m[g] = m;
    __syncthreads();

    // exp
    sE[t]        = expf(g_s[g * BG + t] - m);
    sE[t + 1024] = expf(g_s[g * BG + 1024 + t] - m);
    __syncthreads();

    // column sums: c = t & 63 (coalesced zt rows), jg = t >> 6 owns 128 rows
    const int c = t & 63, jg = t >> 6;
    const int jb = jg * 128;
    float p = 0.0f;
#pragma unroll 4
    for (int j = 0; j < 128; j++)
        p += sE[jb + j] * g_zt[(size_t)(g * BG + jb + j) * 64 + c];
    sP[jg * 68 + c] = p;

    // Ssum partials: threads 64..79 each sum 128 e's
    if (t >= 64 && t < 80) {
        float S = 0.0f;
        const int b0 = (t - 64) * 128;
        for (int j = 0; j < 128; j++) S += sE[b0 + j];
        red[t] = S;
    }
    __syncthreads();

    if (t < 64) {
        float T = 0.0f;
#pragma unroll
        for (int j = 0; j < 16; j++) T += sP[j * 68 + t];
        g_T[g * 64 + t] = T;
    }
    if (t == 0) {
        float S = 0.0f;
#pragma unroll
        for (int j = 64; j < 80; j++) S += red[j];
        g_Ssum[g] = S;
    }
}

// ---------------------------------------------------------------------------
// K3: pred = pooled @ Ww.T + Wwb + c @ Wk.T + Wkb. grid 128, block 256.
// ---------------------------------------------------------------------------
__global__ __launch_bounds__(256) void k3_pred(
    const float* __restrict__ cin,
    const float* __restrict__ Wkw, const float* __restrict__ Wkb,
    const float* __restrict__ Ww0w, const float* __restrict__ Ww0b,
    const float* __restrict__ Ww1w, const float* __restrict__ Ww1b)
{
    __shared__ float sW[128 * 68];
    __shared__ float sU[32 * 68];
    __shared__ float sE[32], sI[32], sB[128];

    const int t = threadIdx.x;
    const int row0 = blockIdx.x * 32;
    const int g = row0 >= BG;
    const int lr0 = row0 - g * BG;
    const float* Www = g ? Ww1w : Ww0w;
    const float* Wwb = g ? Ww1b : Ww0b;

    if (t < 128) sB[t] = Wwb[t] + Wkb[t];
    if (t < 32) {
        float e = expf(g_s[g * BG + lr0 + t] - g_m[g]);
        sE[t] = e;
        sI[t] = 1.0f / (g_Ssum[g] - e);
    }
    {
        const float4* src = (const float4*)Www;
#pragma unroll
        for (int i = 0; i < 8; i++) {
            int idx = t + 256 * i;
            int o = idx >> 4, q = idx & 15;
            *(float4*)&sW[o * 68 + q * 4] = __ldg(src + idx);
        }
    }
    __syncthreads();
    for (int i = t; i < 32 * 64; i += 256) {
        int r = i >> 6, k = i & 63;
        sU[r * 68 + k] = (g_T[g * 64 + k] -
                          sE[r] * g_zt[(size_t)(g * BG + lr0 + r) * 64 + k]) * sI[r];
    }
    __syncthreads();

    const int r = t >> 3, cg = t & 7;
    float acc[16];
#pragma unroll
    for (int i = 0; i < 16; i++) acc[i] = sB[cg + 8 * i];
#pragma unroll 4
    for (int q = 0; q < 16; q++) {
        float4 a = *(const float4*)&sU[r * 68 + q * 4];
#pragma unroll
        for (int i = 0; i < 16; i++) {
            float4 w = *(const float4*)&sW[(cg + 8 * i) * 68 + q * 4];
            acc[i] += a.x * w.x + a.y * w.y + a.z * w.z + a.w * w.w;
        }
    }
    __syncthreads();

    {
        const float4* src = (const float4*)Wkw;
#pragma unroll
        for (int i = 0; i < 8; i++) {
            int idx = t + 256 * i;
            int o = idx >> 4, q = idx & 15;
            *(float4*)&sW[o * 68 + q * 4] = __ldg(src + idx);
        }
        const float4* cu = (const float4*)(cin + (size_t)row0 * 64);
#pragma unroll
        for (int i = 0; i < 2; i++) {
            int idx = t + 256 * i;
            int rr = idx >> 4, q = idx & 15;
            *(float4*)&sU[rr * 68 + q * 4] = __ldg(cu + idx);
        }
    }
    __syncthreads();
#pragma unroll 4
    for (int q = 0; q < 16; q++) {
        float4 a = *(const float4*)&sU[r * 68 + q * 4];
#pragma unroll
        for (int i = 0; i < 16; i++) {
            float4 w = *(const float4*)&sW[(cg + 8 * i) * 68 + q * 4];
            acc[i] += a.x * w.x + a.y * w.y + a.z * w.z + a.w * w.w;
        }
    }
#pragma unroll
    for (int i = 0; i < 16; i++)
        g_pred[(size_t)(row0 + r) * 128 + cg + 8 * i] = acc[i];
}

// ---------------------------------------------------------------------------
// K4: total = zw @ pred.T + fused per-row (max,sumexp) partials + diagonal.
// grid (32, 32), block 256.
//  - tcgen05 path (sm_103a pass): bf16-split hi/lo, fp32 accum in TMEM.
//  - FFMA fallback (plain sm_103 pass): 128x128 tile, 8x8 register blocking.
// ---------------------------------------------------------------------------
#define K4_TILE 16384                      // 128 rows x 128B (64 bf16)
#define K4_SMEM (4 * K4_TILE + 1024 + 64)  // also covers fallback's 33.8KB

__global__ __launch_bounds__(256) void k4_gemm(const float* __restrict__ zw0,
                                               const float* __restrict__ zw1)
{
    extern __shared__ char dsm[];
    const int t = threadIdx.x;
    const int it = blockIdx.y, jt = blockIdx.x;
    const int row0 = it * 128, col0 = jt * 128;
    const float* Ar = (row0 < BG) ? zw0 + (size_t)row0 * 128
                                  : zw1 + (size_t)(row0 - BG) * 128;
    const float* Br = g_pred + (size_t)col0 * 128;

#if K4_TC
    const uint32_t raw = smem_u32(dsm);
    const uint32_t sbase = (raw + 1023u) & ~1023u;
    const uint32_t AHI = sbase, ALO = sbase + K4_TILE;
    const uint32_t BHI = sbase + 2 * K4_TILE, BLO = sbase + 3 * K4_TILE;
    const uint32_t hdr = sbase + 4 * K4_TILE;
    const uint32_t mbar = hdr + 8;

    const int wid = t >> 5, lid = t & 31;

    if (t == 0) MBAR_INIT(mbar, 1);
    if (wid == 0) { TC_ALLOC(hdr, 128); TC_RELINQ(); }
    __syncthreads();
    uint32_t tmem;
    asm volatile("ld.shared.b32 %0, [%1];" : "=r"(tmem) : "r"(hdr));

    // convert: threads 0-127 handle A rows, 128-255 handle B rows
    const int cr = t & 127;
    const float* srcp = (t < 128) ? Ar : Br;
    const float4* sp4 = (const float4*)(srcp + (size_t)cr * 128);
    const uint32_t XH = (t < 128) ? AHI : BHI;
    const uint32_t XL = (t < 128) ? ALO : BLO;
    const uint32_t rb = (uint32_t)cr * 128u;

#pragma unroll 1
    for (int p = 0; p < 2; p++) {
        if (p) MBAR_WAIT(mbar, 0);           // phase-0 MMAs done before reuse
#pragma unroll 4
        for (int q = 0; q < 16; q++) {
            uint32_t so = swz(rb + (uint32_t)q * 8u);
            uint2 hi, lo;
            cvt4(__ldg(sp4 + p * 16 + q), hi, lo);
            *(uint2*)(dsm + (XH + so - raw)) = hi;
            *(uint2*)(dsm + (XL + so - raw)) = lo;
        }
        FENCE_ASYNC();
        __syncthreads();
        if (wid == 0 && elect_one()) {
            uint64_t dAh = make_desc(AHI), dAl = make_desc(ALO);
            uint64_t dBh = make_desc(BHI), dBl = make_desc(BLO);
#pragma unroll
            for (int ks = 0; ks < 4; ks++)
                mma_ss(tmem, dAh + 2 * ks, dBh + 2 * ks, !(p == 0 && ks == 0));
#pragma unroll
            for (int ks = 0; ks < 4; ks++)
                mma_ss(tmem, dAh + 2 * ks, dBl + 2 * ks, true);
#pragma unroll
            for (int ks = 0; ks < 4; ks++)
                mma_ss(tmem, dAl + 2 * ks, dBh + 2 * ks, true);
            TC_COMMIT(mbar);
        }
    }
    MBAR_WAIT(mbar, 1);
    TC_FENCE_AFTER();

    // epilogue: warp w -> subpartition w%4 (rows), column half w/4.
    const int sp = wid & 3, half = wid >> 2;
    const int lrow = sp * 32 + lid;
    const int gi = row0 + lrow;
    const bool dg = (it == jt);
    float M = -1e30f, S = 0.0f;
    uint32_t rr[32];
#pragma unroll 1
    for (int ch = 0; ch < 2; ch++) {
        const int cbase = half * 64 + ch * 32;
        LDTM_X32(rr, tmem + cbase);
        TC_WAIT_LD();
        float cm = -1e30f;
#pragma unroll
        for (int j = 0; j < 32; j++) cm = fmaxf(cm, __uint_as_float(rr[j]));
        if (cm > M) { S *= expf(M - cm); M = cm; }
        float ss = 0.0f;
#pragma unroll
        for (int j = 0; j < 32; j++) ss += expf(__uint_as_float(rr[j]) - M);
        S += ss;
        if (dg && (lrow >> 5) == (half * 2 + ch))
            g_diag[gi] = __uint_as_float(rr[lrow & 31]);
    }
    // combine the two halves per row via smem (smem free now)
    float2* part = (float2*)dsm;             // [128][2]
    part[lrow * 2 + half] = make_float2(M, S);
    __syncthreads();
    if (t < 128) {
        float2 p0 = part[t * 2 + 0], p1 = part[t * 2 + 1];
        float Mf, Sf;
        if (p0.x >= p1.x) { Mf = p0.x; Sf = p0.y + p1.y * expf(p1.x - p0.x); }
        else              { Mf = p1.x; Sf = p1.y + p0.y * expf(p0.x - p1.x); }
        g_pm[(size_t)(row0 + t) * 32 + jt] = Mf;
        g_ps[(size_t)(row0 + t) * 32 + jt] = Sf;
    }

    __syncthreads();
    if (wid == 0) {
        if (elect_one()) MBAR_INVAL(mbar);
        TC_DEALLOC(tmem, 128);
    }
#else
    // ----------------- FFMA fallback (non-'a' compilation pass) -----------
    float* sm = (float*)dsm;                 // 2 * 32*132 floats
    float* sA = sm;
    float* sB = sm + 32 * 132;

    const int ty = t >> 4, tx = t & 15;
    float acc[8][8];
#pragma unroll
    for (int i = 0; i < 8; i++)
#pragma unroll
        for (int j = 0; j < 8; j++) acc[i][j] = 0.0f;

#pragma unroll 1
    for (int kt = 0; kt < 4; kt++) {
#pragma unroll
        for (int i = 0; i < 4; i++) {
            int idx = t + 256 * i;
            int rr2 = idx >> 3;
            int kk = (idx & 7) << 2;
            float4 va = *(const float4*)(Ar + (size_t)rr2 * 128 + kt * 32 + kk);
            sA[(kk + 0) * 132 + rr2] = va.x;
            sA[(kk + 1) * 132 + rr2] = va.y;
            sA[(kk + 2) * 132 + rr2] = va.z;
            sA[(kk + 3) * 132 + rr2] = va.w;
            float4 vb = *(const float4*)(Br + (size_t)rr2 * 128 + kt * 32 + kk);
            sB[(kk + 0) * 132 + rr2] = vb.x;
            sB[(kk + 1) * 132 + rr2] = vb.y;
            sB[(kk + 2) * 132 + rr2] = vb.z;
            sB[(kk + 3) * 132 + rr2] = vb.w;
        }
        __syncthreads();
#pragma unroll 4
        for (int k = 0; k < 32; k++) {
            float4 a0 = *(const float4*)&sA[k * 132 + ty * 8];
            float4 a1 = *(const float4*)&sA[k * 132 + ty * 8 + 4];
            float4 b0 = *(const float4*)&sB[k * 132 + tx * 8];
            float4 b1 = *(const float4*)&sB[k * 132 + tx * 8 + 4];
            float av[8] = {a0.x, a0.y, a0.z, a0.w, a1.x, a1.y, a1.z, a1.w};
            float bv[8] = {b0.x, b0.y, b0.z, b0.w, b1.x, b1.y, b1.z, b1.w};
#pragma unroll
            for (int i = 0; i < 8; i++)
#pragma unroll
                for (int j = 0; j < 8; j++) acc[i][j] += av[i] * bv[j];
        }
        __syncthreads();
    }

    if (it == jt && ty == tx) {
#pragma unroll
        for (int i = 0; i < 8; i++) g_diag[row0 + ty * 8 + i] = acc[i][i];
    }

    float2* red = (float2*)sm;
#pragma unroll
    for (int i = 0; i < 8; i++) {
        float mx = acc[i][0];
#pragma unroll
        for (int j = 1; j < 8; j++) mx = fmaxf(mx, acc[i][j]);
        float ss = 0.0f;
#pragma unroll
        for (int j = 0; j < 8; j++) ss += expf(acc[i][j] - mx);
        red[(ty * 8 + i) * 16 + tx] = make_float2(mx, ss);
    }
    __syncthreads();
    if (t < 128) {
        float M = -1e30f, S = 0.0f;
#pragma unroll
        for (int p = 0; p < 16; p++) {
            float2 v = red[t * 16 + p];
            if (v.x > M) { S = S * expf(M - v.x) + v.y; M = v.x; }
            else         { S += v.y * expf(v.x - M); }
        }
        g_pm[(size_t)(row0 + t) * 32 + jt] = M;
        g_ps[(size_t)(row0 + t) * 32 + jt] = S;
    }
#endif
}

// ---------------------------------------------------------------------------
// K5a: per-128-row partial of sum(lse - diag). grid 32, block 128.
// K5b: final scalar. Deterministic fixed-order everywhere.
// ---------------------------------------------------------------------------
__global__ void k5a_partial()
{
    __shared__ float red[128];
    const int b = blockIdx.x, t = threadIdx.x;
    const int row = b * 128 + t;
    float M = -1e30f, S = 0.0f;
#pragma unroll 4
    for (int p = 0; p < 32; p++) {
        float m = g_pm[(size_t)row * 32 + p];
        float s = g_ps[(size_t)row * 32 + p];
        if (m > M) { S = S * expf(M - m) + s; M = m; }
        else       { S += s * expf(m - M); }
    }
    red[t] = (M + logf(S)) - g_diag[row];
    __syncthreads();
    for (int off = 64; off; off >>= 1) {
        if (t < off) red[t] += red[t + off];
        __syncthreads();
    }
    if (t == 0) g_part[b] = red[0];
}

__global__ void k5b_final(float* __restrict__ out)
{
    if (threadIdx.x == 0) {
        float a = 0.0f;
#pragma unroll
        for (int i = 0; i < 32; i++) a += g_part[i];
        out[0] = a / (float)BT;
    }
}

// ---------------------------------------------------------------------------
extern "C" void kernel_launch(void* const* d_in, const int* in_sizes, int n_in,
                              void* d_out, int out_size)
{
    const float* zw0  = (const float*)d_in[0];
    const float* zw1  = (const float*)d_in[1];
    const float* cin  = (const float*)d_in[2];
    const float* Wkw  = (const float*)d_in[3];
    const float* Wkb  = (const float*)d_in[4];
    const float* Ww0w = (const float*)d_in[5];
    const float* Ww0b = (const float*)d_in[6];
    const float* Ww1w = (const float*)d_in[7];
    const float* Ww1b = (const float*)d_in[8];
    const float* l0w  = (const float*)d_in[9];
    const float* l0b  = (const float*)d_in[10];
    const float* l1w  = (const float*)d_in[11];
    const float* l1b  = (const float*)d_in[12];
    const float* a01w = (const float*)d_in[13];
    const float* a01b = (const float*)d_in[14];
    const float* a02w = (const float*)d_in[15];
    const float* a02b = (const float*)d_in[16];
    const float* a11w = (const float*)d_in[17];
    const float* a11b = (const float*)d_in[18];
    const float* a12w = (const float*)d_in[19];
    const float* a12b = (const float*)d_in[20];

    cudaFuncSetAttribute(k4_gemm, cudaFuncAttributeMaxDynamicSharedMemorySize, K4_SMEM);

    k1_zt_s<<<dim3(64, 2), 256>>>(zw0, zw1, l0w, l0b, l1w, l1b,
                                  a01w, a01b, a02w, a02b,
                                  a11w, a11b, a12w, a12b);
    k2_pool<<<2, 1024>>>();
    k3_pred<<<128, 256>>>(cin, Wkw, Wkb, Ww0w, Ww0b, Ww1w, Ww1b);
    k4_gemm<<<dim3(32, 32), 256, K4_SMEM>>>(zw0, zw1);
    k5a_partial<<<32, 128>>>();
    k5b_final<<<1, 32>>>((float*)d_out);
}

// round 10
// speedup vs baseline: 4.4720x; 1.9033x over previous
#include <cuda_runtime.h>
#include <cuda_bf16.h>
#include <math.h>
#include <stdint.h>

#define BG 2048
#define BT 4096

// Does this compilation pass support tcgen05 (arch-accelerated 'a' features)?
#if defined(__CUDA_ARCH_FEAT_SM103_ALL) || defined(__CUDA_ARCH_FEAT_SM100_ALL) || defined(__CUDA_ARCH_FEAT_SM101_ALL)
#define K4_TC 1
#else
#define K4_TC 0
#endif

// ---------------- scratch ----------------
__device__ float g_zt[2 * BG * 64];
__device__ float g_s[2 * BG];
__device__ float g_m[2];
__device__ float g_Ssum[2];
__device__ float g_T[2 * 64];
__device__ float g_pred[BT * 128];
__device__ float g_pm[BT * 32];
__device__ float g_ps[BT * 32];
__device__ float g_diag[BT];
__device__ float g_part[32];
// pre-converted bf16 hi/lo tiles in SMEM-ready swizzled layout:
// 32 tiles x 2 K-phases x (128 rows x 128B)
__device__ __align__(1024) unsigned char g_Ahi[32 * 2 * 16384];
__device__ __align__(1024) unsigned char g_Alo[32 * 2 * 16384];
__device__ __align__(1024) unsigned char g_Bhi[32 * 2 * 16384];
__device__ __align__(1024) unsigned char g_Blo[32 * 2 * 16384];

// ---------------- helpers ----------------
__device__ __forceinline__ uint32_t smem_u32(const void* p) {
    uint32_t a;
    asm("{ .reg .u64 t; cvta.to.shared.u64 t, %1; cvt.u32.u64 %0, t; }" : "=r"(a) : "l"(p));
    return a;
}
__device__ __forceinline__ bool elect_one() {
    uint32_t p;
    asm volatile("{\n\t.reg .pred p;\n\telect.sync _|p, 0xFFFFFFFF;\n\tselp.b32 %0, 1, 0, p;\n\t}" : "=r"(p));
    return p != 0;
}
__device__ __forceinline__ void cvt4(float4 v, uint2& hi, uint2& lo) {
    __nv_bfloat162 h01 = __floats2bfloat162_rn(v.x, v.y);
    __nv_bfloat162 h23 = __floats2bfloat162_rn(v.z, v.w);
    float2 f01 = __bfloat1622float2(h01);
    float2 f23 = __bfloat1622float2(h23);
    __nv_bfloat162 l01 = __floats2bfloat162_rn(v.x - f01.x, v.y - f01.y);
    __nv_bfloat162 l23 = __floats2bfloat162_rn(v.z - f23.x, v.w - f23.y);
    hi.x = *reinterpret_cast<uint32_t*>(&h01);
    hi.y = *reinterpret_cast<uint32_t*>(&h23);
    lo.x = *reinterpret_cast<uint32_t*>(&l01);
    lo.y = *reinterpret_cast<uint32_t*>(&l23);
}
__device__ __forceinline__ uint32_t swz(uint32_t b) { return b ^ ((b >> 3) & 0x70); }

#define MBAR_INIT(a, c) asm volatile("mbarrier.init.shared.b64 [%0], %1;" :: "r"(a), "r"((uint32_t)(c)) : "memory")
#define MBAR_INVAL(a)   asm volatile("mbarrier.inval.shared.b64 [%0];" :: "r"(a) : "memory")
#define MBAR_WAIT(mb, ph) do { \
    uint32_t _m = (uint32_t)(mb), _p = (uint32_t)(ph), _d; \
    asm volatile("{\n\t.reg .pred p;\n\tmbarrier.try_wait.parity.acquire.cta.shared::cta.b64 p, [%1], %2;\n\tselp.b32 %0, 1, 0, p;\n\t}" \
        : "=r"(_d) : "r"(_m), "r"(_p) : "memory"); \
    if (!_d) { \
        asm volatile("{\n\t.reg .pred P1;\n\tWL_%=:\n\tmbarrier.try_wait.parity.acquire.cta.shared::cta.b64 P1, [%0], %1, 0x989680;\n\t@P1 bra.uni WD_%=;\n\tbra.uni WL_%=;\n\tWD_%=:\n\t}" \
            :: "r"(_m), "r"(_p) : "memory"); \
    } } while (0)

#if K4_TC
#define TC_ALLOC(a, n)  asm volatile("tcgen05.alloc.cta_group::1.sync.aligned.shared::cta.b32 [%0], %1;" :: "r"(a), "r"((uint32_t)(n)) : "memory")
#define TC_RELINQ()     asm volatile("tcgen05.relinquish_alloc_permit.cta_group::1.sync.aligned;")
#define TC_DEALLOC(t, n) asm volatile("tcgen05.dealloc.cta_group::1.sync.aligned.b32 %0, %1;" :: "r"(t), "r"((uint32_t)(n)))
#define TC_COMMIT(mb)   asm volatile("tcgen05.commit.cta_group::1.mbarrier::arrive::one.shared::cluster.b64 [%0];" :: "r"(mb) : "memory")
#define TC_FENCE_AFTER() asm volatile("tcgen05.fence::after_thread_sync;" ::: "memory")
#define TC_WAIT_LD()    asm volatile("tcgen05.wait::ld.sync.aligned;" ::: "memory")
#define FENCE_ASYNC()   asm volatile("fence.proxy.async.shared::cta;" ::: "memory")

#define LDTM_X32(r, ta) \
    asm volatile("tcgen05.ld.sync.aligned.32x32b.x32.b32 " \
        "{%0, %1, %2, %3, %4, %5, %6, %7, %8, %9, %10, %11, %12, %13, %14, %15, " \
        " %16, %17, %18, %19, %20, %21, %22, %23, %24, %25, %26, %27, %28, %29, %30, %31}, [%32];" \
        : "=r"((r)[0]),  "=r"((r)[1]),  "=r"((r)[2]),  "=r"((r)[3]), \
          "=r"((r)[4]),  "=r"((r)[5]),  "=r"((r)[6]),  "=r"((r)[7]), \
          "=r"((r)[8]),  "=r"((r)[9]),  "=r"((r)[10]), "=r"((r)[11]), \
          "=r"((r)[12]), "=r"((r)[13]), "=r"((r)[14]), "=r"((r)[15]), \
          "=r"((r)[16]), "=r"((r)[17]), "=r"((r)[18]), "=r"((r)[19]), \
          "=r"((r)[20]), "=r"((r)[21]), "=r"((r)[22]), "=r"((r)[23]), \
          "=r"((r)[24]), "=r"((r)[25]), "=r"((r)[26]), "=r"((r)[27]), \
          "=r"((r)[28]), "=r"((r)[29]), "=r"((r)[30]), "=r"((r)[31]) \
        : "r"(ta))

__device__ __forceinline__ uint64_t make_desc(uint32_t addr) {
    // SW128, Blackwell v1, SBO=64 (1024B), LBO=1 (16B)
    const uint64_t base = (2ull << 61) | (1ull << 46) | (64ull << 32) | (1ull << 16);
    return base | ((uint64_t)(addr >> 4) & 0x3FFF);
}
// kind::f16, dtype=F32, a=b=BF16, N=128, M=128 (validated round 7)
#define IDESC_K4 ((1u << 4) | (1u << 7) | (1u << 10) | ((128u / 8) << 17) | ((128u / 16) << 24))

__device__ __forceinline__ void mma_ss(uint32_t d, uint64_t ad, uint64_t bd, bool en) {
    uint32_t e = en ? 1u : 0u;
    asm volatile(
        "{\n\t.reg .pred p;\n\tsetp.ne.u32 p, %4, 0;\n\t"
        "tcgen05.mma.cta_group::1.kind::f16 [%0], %1, %2, %3, {%5, %5, %5, %5}, p;\n\t}"
        :: "r"(d), "l"(ad), "l"(bd), "r"(IDESC_K4), "r"(e), "r"(0u) : "memory");
}
#endif  // K4_TC

// ---------------------------------------------------------------------------
// kc_conv: split fp32 rows into swizzled bf16 hi/lo tile blocks (once).
// grid 128, block 256. blocks 0-63: A (zw rows), 64-127: B (pred rows).
// block -> (tile 0..31 of 128 rows, K-phase 0..1).
// ---------------------------------------------------------------------------
__global__ __launch_bounds__(256) void kc_conv(const float* __restrict__ zw0,
                                               const float* __restrict__ zw1)
{
    const int bp = blockIdx.x;
    const int isB = bp >> 6;
    const int x = bp & 63;
    const int tile = x >> 1, p = x & 1;
    const int t = threadIdx.x;

    const float4* src;
    int rbase;
    unsigned char *dhi, *dlo;
    if (!isB) {
        src = (tile < 16) ? (const float4*)zw0 : (const float4*)zw1;
        rbase = (tile & 15) * 128;
        dhi = g_Ahi + (size_t)x * 16384;
        dlo = g_Alo + (size_t)x * 16384;
    } else {
        src = (const float4*)g_pred;
        rbase = tile * 128;
        dhi = g_Bhi + (size_t)x * 16384;
        dlo = g_Blo + (size_t)x * 16384;
    }
#pragma unroll
    for (int i = 0; i < 8; i++) {
        int c = t + 256 * i;               // 0..2047
        int lr = c >> 4, kq = c & 15;
        float4 v = __ldg(src + (size_t)(rbase + lr) * 32 + p * 16 + kq);
        uint2 hi, lo; cvt4(v, hi, lo);
        uint32_t off = swz((uint32_t)(lr * 128 + kq * 8));
        *(uint2*)(dhi + off) = hi;
        *(uint2*)(dlo + off) = lo;
    }
}

// ---------------------------------------------------------------------------
// K1: zt = relu(zw @ lw.T + lb); s = tanh(zt@a1.T+a1b)@a2 + a2b
// grid (64, 2), block 256. a1w staged transposed in smem.
// ---------------------------------------------------------------------------
__global__ __launch_bounds__(256) void k1_zt_s(
    const float* __restrict__ zw0, const float* __restrict__ zw1,
    const float* __restrict__ l0w, const float* __restrict__ l0b,
    const float* __restrict__ l1w, const float* __restrict__ l1b,
    const float* __restrict__ a01w, const float* __restrict__ a01b,
    const float* __restrict__ a02w, const float* __restrict__ a02b,
    const float* __restrict__ a11w, const float* __restrict__ a11b,
    const float* __restrict__ a12w, const float* __restrict__ a12b)
{
    __shared__ float sLW[64 * 132];
    __shared__ float sZT[32 * 65];
    __shared__ float sA1T[64 * 33];

    const int g = blockIdx.y;
    const float* zw  = g ? zw1  : zw0;
    const float* lw  = g ? l1w  : l0w;
    const float* lb  = g ? l1b  : l0b;
    const float* a1w = g ? a11w : a01w;
    const float* a1b = g ? a11b : a01b;
    const float* a2w = g ? a12w : a02w;
    const float* a2b = g ? a12b : a02b;

    const int t = threadIdx.x;
    const int r0 = blockIdx.x * 32;

    {
        const float4* src = (const float4*)lw;
#pragma unroll
        for (int i = 0; i < 8; i++) {
            int idx = t + 256 * i;
            int o = idx >> 5, q = idx & 31;
            *(float4*)&sLW[o * 132 + q * 4] = __ldg(src + idx);
        }
    }
    for (int i = t; i < 2048; i += 256) {
        int o = i >> 6, k = i & 63;
        sA1T[k * 33 + o] = __ldg(a1w + i);
    }
    __syncthreads();

    const int r = t >> 3, cg = t & 7;
    float acc[8];
#pragma unroll
    for (int i = 0; i < 8; i++) acc[i] = __ldg(lb + cg + 8 * i);

    const float4* zp = (const float4*)(zw + (size_t)(r0 + r) * 128);
#pragma unroll 8
    for (int q = 0; q < 32; q++) {
        float4 a = __ldg(zp + q);
#pragma unroll
        for (int i = 0; i < 8; i++) {
            float4 w = *(const float4*)&sLW[(cg + 8 * i) * 132 + q * 4];
            acc[i] += a.x * w.x + a.y * w.y + a.z * w.z + a.w * w.w;
        }
    }
#pragma unroll
    for (int i = 0; i < 8; i++) {
        float v = fmaxf(acc[i], 0.0f);
        sZT[r * 65 + cg + 8 * i] = v;
        g_zt[(size_t)(g * BG + r0 + r) * 64 + cg + 8 * i] = v;
    }
    __syncthreads();

    const int w = t >> 5, lane = t & 31;
    const float a2v  = __ldg(a2w + lane);
    const float a1bv = __ldg(a1b + lane);
    const float a2bv = __ldg(a2b);
    for (int rr = 0; rr < 4; rr++) {
        const int row = w * 4 + rr;
        float d = a1bv;
#pragma unroll 8
        for (int k = 0; k < 64; k++)
            d += sZT[row * 65 + k] * sA1T[k * 33 + lane];
        float v = tanhf(d) * a2v;
#pragma unroll
        for (int off = 16; off; off >>= 1) v += __shfl_down_sync(0xffffffffu, v, off);
        if (lane == 0) g_s[g * BG + r0 + row] = v + a2bv;
    }
}

// ---------------------------------------------------------------------------
// K2: per group: m = max(s); e = exp(s-m); T[c] = sum e*zt[:,c]; Ssum = sum e.
// ---------------------------------------------------------------------------
__global__ __launch_bounds__(1024) void k2_pool()
{
    __shared__ float sE[2048];
    __shared__ float red[1024];
    __shared__ float sP[16 * 68];

    const int g = blockIdx.x, t = threadIdx.x;

    float a = fmaxf(g_s[g * BG + t], g_s[g * BG + 1024 + t]);
    red[t] = a; __syncthreads();
    for (int off = 512; off; off >>= 1) {
        if (t < off) red[t] = fmaxf(red[t], red[t + off]);
        __syncthreads();
    }
    const float m = red[0];
    if (t == 0) g_m[g] = m;
    __syncthreads();

    sE[t]        = expf(g_s[g * BG + t] - m);
    sE[t + 1024] = expf(g_s[g * BG + 1024 + t] - m);
    __syncthreads();

    const int c = t & 63, jg = t >> 6;
    const int jb = jg * 128;
    float p = 0.0f;
#pragma unroll 4
    for (int j = 0; j < 128; j++)
        p += sE[jb + j] * g_zt[(size_t)(g * BG + jb + j) * 64 + c];
    sP[jg * 68 + c] = p;

    if (t >= 64 && t < 80) {
        float S = 0.0f;
        const int b0 = (t - 64) * 128;
        for (int j = 0; j < 128; j++) S += sE[b0 + j];
        red[t] = S;
    }
    __syncthreads();

    if (t < 64) {
        float T = 0.0f;
#pragma unroll
        for (int j = 0; j < 16; j++) T += sP[j * 68 + t];
        g_T[g * 64 + t] = T;
    }
    if (t == 0) {
        float S = 0.0f;
#pragma unroll
        for (int j = 64; j < 80; j++) S += red[j];
        g_Ssum[g] = S;
    }
}

// ---------------------------------------------------------------------------
// K3: pred = pooled @ Ww.T + Wwb + c @ Wk.T + Wkb. grid 128, block 256.
// ---------------------------------------------------------------------------
__global__ __launch_bounds__(256) void k3_pred(
    const float* __restrict__ cin,
    const float* __restrict__ Wkw, const float* __restrict__ Wkb,
    const float* __restrict__ Ww0w, const float* __restrict__ Ww0b,
    const float* __restrict__ Ww1w, const float* __restrict__ Ww1b)
{
    __shared__ float sW[128 * 68];
    __shared__ float sU[32 * 68];
    __shared__ float sE[32], sI[32], sB[128];

    const int t = threadIdx.x;
    const int row0 = blockIdx.x * 32;
    const int g = row0 >= BG;
    const int lr0 = row0 - g * BG;
    const float* Www = g ? Ww1w : Ww0w;
    const float* Wwb = g ? Ww1b : Ww0b;

    if (t < 128) sB[t] = Wwb[t] + Wkb[t];
    if (t < 32) {
        float e = expf(g_s[g * BG + lr0 + t] - g_m[g]);
        sE[t] = e;
        sI[t] = 1.0f / (g_Ssum[g] - e);
    }
    {
        const float4* src = (const float4*)Www;
#pragma unroll
        for (int i = 0; i < 8; i++) {
            int idx = t + 256 * i;
            int o = idx >> 4, q = idx & 15;
            *(float4*)&sW[o * 68 + q * 4] = __ldg(src + idx);
        }
    }
    __syncthreads();
    for (int i = t; i < 32 * 64; i += 256) {
        int r = i >> 6, k = i & 63;
        sU[r * 68 + k] = (g_T[g * 64 + k] -
                          sE[r] * g_zt[(size_t)(g * BG + lr0 + r) * 64 + k]) * sI[r];
    }
    __syncthreads();

    const int r = t >> 3, cg = t & 7;
    float acc[16];
#pragma unroll
    for (int i = 0; i < 16; i++) acc[i] = sB[cg + 8 * i];
#pragma unroll 4
    for (int q = 0; q < 16; q++) {
        float4 a = *(const float4*)&sU[r * 68 + q * 4];
#pragma unroll
        for (int i = 0; i < 16; i++) {
            float4 w = *(const float4*)&sW[(cg + 8 * i) * 68 + q * 4];
            acc[i] += a.x * w.x + a.y * w.y + a.z * w.z + a.w * w.w;
        }
    }
    __syncthreads();

    {
        const float4* src = (const float4*)Wkw;
#pragma unroll
        for (int i = 0; i < 8; i++) {
            int idx = t + 256 * i;
            int o = idx >> 4, q = idx & 15;
            *(float4*)&sW[o * 68 + q * 4] = __ldg(src + idx);
        }
        const float4* cu = (const float4*)(cin + (size_t)row0 * 64);
#pragma unroll
        for (int i = 0; i < 2; i++) {
            int idx = t + 256 * i;
            int rr = idx >> 4, q = idx & 15;
            *(float4*)&sU[rr * 68 + q * 4] = __ldg(cu + idx);
        }
    }
    __syncthreads();
#pragma unroll 4
    for (int q = 0; q < 16; q++) {
        float4 a = *(const float4*)&sU[r * 68 + q * 4];
#pragma unroll
        for (int i = 0; i < 16; i++) {
            float4 w = *(const float4*)&sW[(cg + 8 * i) * 68 + q * 4];
            acc[i] += a.x * w.x + a.y * w.y + a.z * w.z + a.w * w.w;
        }
    }
#pragma unroll
    for (int i = 0; i < 16; i++)
        g_pred[(size_t)(row0 + r) * 128 + cg + 8 * i] = acc[i];
}

// ---------------------------------------------------------------------------
// K4: total = zw @ pred.T (128x128 tiles) + fused (max,sumexp) + diag.
// grid (32, 32), block 256. Round-7-proven skeleton; tile fill is now a 1:1
// uint4 copy of pre-converted bf16 tiles (phase-1 LDGs issued before the
// phase-0 MMA wait to hide L2 latency behind tensor work).
// ---------------------------------------------------------------------------
#define K4_TILE 16384
#define K4_SMEM (4 * K4_TILE + 1024 + 64)

__global__ __launch_bounds__(256) void k4_gemm(const float* __restrict__ zw0,
                                               const float* __restrict__ zw1)
{
    extern __shared__ char dsm[];
    const int t = threadIdx.x;
    const int it = blockIdx.y, jt = blockIdx.x;
    const int row0 = it * 128, col0 = jt * 128;

#if K4_TC
    const uint32_t raw = smem_u32(dsm);
    const uint32_t sbase = (raw + 1023u) & ~1023u;
    const uint32_t AHI = sbase, ALO = sbase + K4_TILE;
    const uint32_t BHI = sbase + 2 * K4_TILE, BLO = sbase + 3 * K4_TILE;
    const uint32_t hdr = sbase + 4 * K4_TILE;
    const uint32_t mbar = hdr + 8;
    const int wid = t >> 5, lid = t & 31;

    if (t == 0) MBAR_INIT(mbar, 1);
    if (wid == 0) { TC_ALLOC(hdr, 128); TC_RELINQ(); }
    __syncthreads();
    uint32_t tmem;
    asm volatile("ld.shared.b32 %0, [%1];" : "=r"(tmem) : "r"(hdr));

    uint4* sAh = (uint4*)(dsm + (AHI - raw));
    uint4* sAl = (uint4*)(dsm + (ALO - raw));
    uint4* sBh = (uint4*)(dsm + (BHI - raw));
    uint4* sBl = (uint4*)(dsm + (BLO - raw));

#pragma unroll 1
    for (int p = 0; p < 2; p++) {
        const uint4* gAh = (const uint4*)(g_Ahi + (size_t)(it * 2 + p) * K4_TILE);
        const uint4* gAl = (const uint4*)(g_Alo + (size_t)(it * 2 + p) * K4_TILE);
        const uint4* gBh = (const uint4*)(g_Bhi + (size_t)(jt * 2 + p) * K4_TILE);
        const uint4* gBl = (const uint4*)(g_Blo + (size_t)(jt * 2 + p) * K4_TILE);
        uint4 rAh[4], rAl[4], rBh[4], rBl[4];
#pragma unroll
        for (int j = 0; j < 4; j++) {
            int idx = t + 256 * j;
            rAh[j] = __ldg(gAh + idx);
            rAl[j] = __ldg(gAl + idx);
            rBh[j] = __ldg(gBh + idx);
            rBl[j] = __ldg(gBl + idx);
        }
        if (p) MBAR_WAIT(mbar, 0);           // phase-0 MMAs done before reuse
#pragma unroll
        for (int j = 0; j < 4; j++) {
            int idx = t + 256 * j;
            sAh[idx] = rAh[j];
            sAl[idx] = rAl[j];
            sBh[idx] = rBh[j];
            sBl[idx] = rBl[j];
        }
        FENCE_ASYNC();
        __syncthreads();
        if (wid == 0 && elect_one()) {
            uint64_t dAh = make_desc(AHI), dAl = make_desc(ALO);
            uint64_t dBh = make_desc(BHI), dBl = make_desc(BLO);
#pragma unroll
            for (int ks = 0; ks < 4; ks++)
                mma_ss(tmem, dAh + 2 * ks, dBh + 2 * ks, !(p == 0 && ks == 0));
#pragma unroll
            for (int ks = 0; ks < 4; ks++)
                mma_ss(tmem, dAh + 2 * ks, dBl + 2 * ks, true);
#pragma unroll
            for (int ks = 0; ks < 4; ks++)
                mma_ss(tmem, dAl + 2 * ks, dBh + 2 * ks, true);
            TC_COMMIT(mbar);
        }
    }
    MBAR_WAIT(mbar, 1);
    TC_FENCE_AFTER();

    // epilogue (round-7 proven): warp -> (subpartition, column half), 2 chunks.
    const int sp = wid & 3, half = wid >> 2;
    const int lrow = sp * 32 + lid;
    const int gi = row0 + lrow;
    const bool dg = (it == jt);
    float M = -1e30f, S = 0.0f;
    uint32_t rr[32];
#pragma unroll 1
    for (int ch = 0; ch < 2; ch++) {
        LDTM_X32(rr, tmem + half * 64 + ch * 32);
        TC_WAIT_LD();
        float cm = -1e30f;
#pragma unroll
        for (int j = 0; j < 32; j++) cm = fmaxf(cm, __uint_as_float(rr[j]));
        if (cm > M) { S *= __expf(M - cm); M = cm; }
        float ss = 0.0f;
#pragma unroll
        for (int j = 0; j < 32; j++) ss += __expf(__uint_as_float(rr[j]) - M);
        S += ss;
        if (dg && (lrow >> 5) == (half * 2 + ch))
            g_diag[gi] = __uint_as_float(rr[lrow & 31]);
    }
    float2* part = (float2*)dsm;             // [128][2], tiles free now
    part[lrow * 2 + half] = make_float2(M, S);
    __syncthreads();
    if (t < 128) {
        float2 p0 = part[t * 2 + 0], p1 = part[t * 2 + 1];
        float Mf, Sf;
        if (p0.x >= p1.x) { Mf = p0.x; Sf = p0.y + p1.y * __expf(p1.x - p0.x); }
        else              { Mf = p1.x; Sf = p1.y + p0.y * __expf(p0.x - p1.x); }
        g_pm[(size_t)(row0 + t) * 32 + jt] = Mf;
        g_ps[(size_t)(row0 + t) * 32 + jt] = Sf;
    }
    __syncthreads();
    if (t == 0) MBAR_INVAL(mbar);
    if (wid == 0) TC_DEALLOC(tmem, 128);
#else
    // ----------------- FFMA fallback (non-'a' pass) ------------------------
    float* smf = (float*)dsm;
    float* sA = smf;
    float* sB = smf + 32 * 132;
    const float* Ar = (row0 < BG) ? zw0 + (size_t)row0 * 128
                                  : zw1 + (size_t)(row0 - BG) * 128;
    const float* Br = g_pred + (size_t)col0 * 128;

    const int ty = t >> 4, tx = t & 15;
    float acc[8][8];
#pragma unroll
    for (int i = 0; i < 8; i++)
#pragma unroll
        for (int j = 0; j < 8; j++) acc[i][j] = 0.0f;

#pragma unroll 1
    for (int kt = 0; kt < 4; kt++) {
#pragma unroll
        for (int i = 0; i < 4; i++) {
            int idx = t + 256 * i;
            int rr2 = idx >> 3;
            int kk = (idx & 7) << 2;
            float4 va = *(const float4*)(Ar + (size_t)rr2 * 128 + kt * 32 + kk);
            sA[(kk + 0) * 132 + rr2] = va.x;
            sA[(kk + 1) * 132 + rr2] = va.y;
            sA[(kk + 2) * 132 + rr2] = va.z;
            sA[(kk + 3) * 132 + rr2] = va.w;
            float4 vb = *(const float4*)(Br + (size_t)rr2 * 128 + kt * 32 + kk);
            sB[(kk + 0) * 132 + rr2] = vb.x;
            sB[(kk + 1) * 132 + rr2] = vb.y;
            sB[(kk + 2) * 132 + rr2] = vb.z;
            sB[(kk + 3) * 132 + rr2] = vb.w;
        }
        __syncthreads();
#pragma unroll 4
        for (int k = 0; k < 32; k++) {
            float4 a0 = *(const float4*)&sA[k * 132 + ty * 8];
            float4 a1 = *(const float4*)&sA[k * 132 + ty * 8 + 4];
            float4 b0 = *(const float4*)&sB[k * 132 + tx * 8];
            float4 b1 = *(const float4*)&sB[k * 132 + tx * 8 + 4];
            float av[8] = {a0.x, a0.y, a0.z, a0.w, a1.x, a1.y, a1.z, a1.w};
            float bv[8] = {b0.x, b0.y, b0.z, b0.w, b1.x, b1.y, b1.z, b1.w};
#pragma unroll
            for (int i = 0; i < 8; i++)
#pragma unroll
                for (int j = 0; j < 8; j++) acc[i][j] += av[i] * bv[j];
        }
        __syncthreads();
    }

    if (it == jt && ty == tx) {
#pragma unroll
        for (int i = 0; i < 8; i++) g_diag[row0 + ty * 8 + i] = acc[i][i];
    }
    float2* red = (float2*)smf;
#pragma unroll
    for (int i = 0; i < 8; i++) {
        float mx = acc[i][0];
#pragma unroll
        for (int j = 1; j < 8; j++) mx = fmaxf(mx, acc[i][j]);
        float ss = 0.0f;
#pragma unroll
        for (int j = 0; j < 8; j++) ss += expf(acc[i][j] - mx);
        red[(ty * 8 + i) * 16 + tx] = make_float2(mx, ss);
    }
    __syncthreads();
    if (t < 128) {
        float M = -1e30f, S = 0.0f;
#pragma unroll
        for (int p = 0; p < 16; p++) {
            float2 v = red[t * 16 + p];
            if (v.x > M) { S = S * expf(M - v.x) + v.y; M = v.x; }
            else         { S += v.y * expf(v.x - M); }
        }
        g_pm[(size_t)(row0 + t) * 32 + jt] = M;
        g_ps[(size_t)(row0 + t) * 32 + jt] = S;
    }
#endif
}

// ---------------------------------------------------------------------------
// K5a: per-128-row partial of sum(lse - diag). grid 32, block 128.
// ---------------------------------------------------------------------------
__global__ void k5a_partial()
{
    __shared__ float red[128];
    const int b = blockIdx.x, t = threadIdx.x;
    const int row = b * 128 + t;
    float M = -1e30f, S = 0.0f;
#pragma unroll 4
    for (int p = 0; p < 32; p++) {
        float m = g_pm[(size_t)row * 32 + p];
        float s = g_ps[(size_t)row * 32 + p];
        if (m > M) { S = S * expf(M - m) + s; M = m; }
        else       { S += s * expf(m - M); }
    }
    red[t] = (M + logf(S)) - g_diag[row];
    __syncthreads();
    for (int off = 64; off; off >>= 1) {
        if (t < off) red[t] += red[t + off];
        __syncthreads();
    }
    if (t == 0) g_part[b] = red[0];
}

__global__ void k5b_final(float* __restrict__ out)
{
    if (threadIdx.x == 0) {
        float a = 0.0f;
#pragma unroll
        for (int i = 0; i < 32; i++) a += g_part[i];
        out[0] = a / (float)BT;
    }
}

// ---------------------------------------------------------------------------
extern "C" void kernel_launch(void* const* d_in, const int* in_sizes, int n_in,
                              void* d_out, int out_size)
{
    const float* zw0  = (const float*)d_in[0];
    const float* zw1  = (const float*)d_in[1];
    const float* cin  = (const float*)d_in[2];
    const float* Wkw  = (const float*)d_in[3];
    const float* Wkb  = (const float*)d_in[4];
    const float* Ww0w = (const float*)d_in[5];
    const float* Ww0b = (const float*)d_in[6];
    const float* Ww1w = (const float*)d_in[7];
    const float* Ww1b = (const float*)d_in[8];
    const float* l0w  = (const float*)d_in[9];
    const float* l0b  = (const float*)d_in[10];
    const float* l1w  = (const float*)d_in[11];
    const float* l1b  = (const float*)d_in[12];
    const float* a01w = (const float*)d_in[13];
    const float* a01b = (const float*)d_in[14];
    const float* a02w = (const float*)d_in[15];
    const float* a02b = (const float*)d_in[16];
    const float* a11w = (const float*)d_in[17];
    const float* a11b = (const float*)d_in[18];
    const float* a12w = (const float*)d_in[19];
    const float* a12b = (const float*)d_in[20];

    cudaFuncSetAttribute(k4_gemm, cudaFuncAttributeMaxDynamicSharedMemorySize, K4_SMEM);

    k1_zt_s<<<dim3(64, 2), 256>>>(zw0, zw1, l0w, l0b, l1w, l1b,
                                  a01w, a01b, a02w, a02b,
                                  a11w, a11b, a12w, a12b);
    k2_pool<<<2, 1024>>>();
    k3_pred<<<128, 256>>>(cin, Wkw, Wkb, Ww0w, Ww0b, Ww1w, Ww1b);
    kc_conv<<<128, 256>>>(zw0, zw1);
    k4_gemm<<<dim3(32, 32), 256, K4_SMEM>>>(zw0, zw1);
    k5a_partial<<<32, 128>>>();
    k5b_final<<<1, 32>>>((float*)d_out);
}

// round 13
// speedup vs baseline: 5.0656x; 1.1327x over previous
#include <cuda_runtime.h>
#include <cuda_bf16.h>
#include <math.h>
#include <stdint.h>

#define BG 2048
#define BT 4096

// Does this compilation pass support tcgen05 (arch-accelerated 'a' features)?
#if defined(__CUDA_ARCH_FEAT_SM103_ALL) || defined(__CUDA_ARCH_FEAT_SM100_ALL) || defined(__CUDA_ARCH_FEAT_SM101_ALL)
#define K4_TC 1
#else
#define K4_TC 0
#endif

// ---------------- scratch ----------------
__device__ float g_zt[2 * BG * 64];
__device__ float g_s[2 * BG];
__device__ float g_m[2];
__device__ float g_Ssum[2];
__device__ float g_T[2 * 64];
__device__ float g_mp[32];          // per-chunk max
__device__ float g_Sp2[32];         // per-chunk sum exp
__device__ float g_Tp[32 * 64];     // per-chunk weighted zt sums
__device__ float g_pred[BT * 128];
__device__ float g_pm[BT * 16];
__device__ float g_ps[BT * 16];
__device__ float g_diag[BT];
__device__ float g_part[32];
// pre-converted bf16 hi/lo tiles in SMEM-ready swizzled layout:
// 32 tiles x 2 K-phases x (128 rows x 128B)
__device__ __align__(1024) unsigned char g_Ahi[32 * 2 * 16384];
__device__ __align__(1024) unsigned char g_Alo[32 * 2 * 16384];
__device__ __align__(1024) unsigned char g_Bhi[32 * 2 * 16384];
__device__ __align__(1024) unsigned char g_Blo[32 * 2 * 16384];

// ---------------- helpers ----------------
__device__ __forceinline__ uint32_t smem_u32(const void* p) {
    uint32_t a;
    asm("{ .reg .u64 t; cvta.to.shared.u64 t, %1; cvt.u32.u64 %0, t; }" : "=r"(a) : "l"(p));
    return a;
}
__device__ __forceinline__ bool elect_one() {
    uint32_t p;
    asm volatile("{\n\t.reg .pred p;\n\telect.sync _|p, 0xFFFFFFFF;\n\tselp.b32 %0, 1, 0, p;\n\t}" : "=r"(p));
    return p != 0;
}
__device__ __forceinline__ void cvt4(float4 v, uint2& hi, uint2& lo) {
    __nv_bfloat162 h01 = __floats2bfloat162_rn(v.x, v.y);
    __nv_bfloat162 h23 = __floats2bfloat162_rn(v.z, v.w);
    float2 f01 = __bfloat1622float2(h01);
    float2 f23 = __bfloat1622float2(h23);
    __nv_bfloat162 l01 = __floats2bfloat162_rn(v.x - f01.x, v.y - f01.y);
    __nv_bfloat162 l23 = __floats2bfloat162_rn(v.z - f23.x, v.w - f23.y);
    hi.x = *reinterpret_cast<uint32_t*>(&h01);
    hi.y = *reinterpret_cast<uint32_t*>(&h23);
    lo.x = *reinterpret_cast<uint32_t*>(&l01);
    lo.y = *reinterpret_cast<uint32_t*>(&l23);
}
__device__ __forceinline__ uint32_t swz(uint32_t b) { return b ^ ((b >> 3) & 0x70); }

#define MBAR_INIT(a, c) asm volatile("mbarrier.init.shared.b64 [%0], %1;" :: "r"(a), "r"((uint32_t)(c)) : "memory")
#define MBAR_INVAL(a)   asm volatile("mbarrier.inval.shared.b64 [%0];" :: "r"(a) : "memory")
#define MBAR_WAIT(mb, ph) do { \
    uint32_t _m = (uint32_t)(mb), _p = (uint32_t)(ph), _d; \
    asm volatile("{\n\t.reg .pred p;\n\tmbarrier.try_wait.parity.acquire.cta.shared::cta.b64 p, [%1], %2;\n\tselp.b32 %0, 1, 0, p;\n\t}" \
        : "=r"(_d) : "r"(_m), "r"(_p) : "memory"); \
    if (!_d) { \
        asm volatile("{\n\t.reg .pred P1;\n\tWL_%=:\n\tmbarrier.try_wait.parity.acquire.cta.shared::cta.b64 P1, [%0], %1, 0x989680;\n\t@P1 bra.uni WD_%=;\n\tbra.uni WL_%=;\n\tWD_%=:\n\t}" \
            :: "r"(_m), "r"(_p) : "memory"); \
    } } while (0)

#if K4_TC
#define TC_ALLOC(a, n)  asm volatile("tcgen05.alloc.cta_group::1.sync.aligned.shared::cta.b32 [%0], %1;" :: "r"(a), "r"((uint32_t)(n)) : "memory")
#define TC_RELINQ()     asm volatile("tcgen05.relinquish_alloc_permit.cta_group::1.sync.aligned;")
#define TC_DEALLOC(t, n) asm volatile("tcgen05.dealloc.cta_group::1.sync.aligned.b32 %0, %1;" :: "r"(t), "r"((uint32_t)(n)))
#define TC_COMMIT(mb)   asm volatile("tcgen05.commit.cta_group::1.mbarrier::arrive::one.shared::cluster.b64 [%0];" :: "r"(mb) : "memory")
#define TC_FENCE_AFTER() asm volatile("tcgen05.fence::after_thread_sync;" ::: "memory")
#define TC_WAIT_LD()    asm volatile("tcgen05.wait::ld.sync.aligned;" ::: "memory")
#define FENCE_ASYNC()   asm volatile("fence.proxy.async.shared::cta;" ::: "memory")

#define LDTM_X32(r, ta) \
    asm volatile("tcgen05.ld.sync.aligned.32x32b.x32.b32 " \
        "{%0, %1, %2, %3, %4, %5, %6, %7, %8, %9, %10, %11, %12, %13, %14, %15, " \
        " %16, %17, %18, %19, %20, %21, %22, %23, %24, %25, %26, %27, %28, %29, %30, %31}, [%32];" \
        : "=r"((r)[0]),  "=r"((r)[1]),  "=r"((r)[2]),  "=r"((r)[3]), \
          "=r"((r)[4]),  "=r"((r)[5]),  "=r"((r)[6]),  "=r"((r)[7]), \
          "=r"((r)[8]),  "=r"((r)[9]),  "=r"((r)[10]), "=r"((r)[11]), \
          "=r"((r)[12]), "=r"((r)[13]), "=r"((r)[14]), "=r"((r)[15]), \
          "=r"((r)[16]), "=r"((r)[17]), "=r"((r)[18]), "=r"((r)[19]), \
          "=r"((r)[20]), "=r"((r)[21]), "=r"((r)[22]), "=r"((r)[23]), \
          "=r"((r)[24]), "=r"((r)[25]), "=r"((r)[26]), "=r"((r)[27]), \
          "=r"((r)[28]), "=r"((r)[29]), "=r"((r)[30]), "=r"((r)[31]) \
        : "r"(ta))

__device__ __forceinline__ uint64_t make_desc(uint32_t addr) {
    // SW128, Blackwell v1, SBO=64 (1024B), LBO=1 (16B)
    const uint64_t base = (2ull << 61) | (1ull << 46) | (64ull << 32) | (1ull << 16);
    return base | ((uint64_t)(addr >> 4) & 0x3FFF);
}
// kind::f16, dtype=F32, a=b=BF16, N=128, M=128 (validated round 7)
#define IDESC_K4 ((1u << 4) | (1u << 7) | (1u << 10) | ((128u / 8) << 17) | ((128u / 16) << 24))

__device__ __forceinline__ void mma_ss(uint32_t d, uint64_t ad, uint64_t bd, bool en) {
    uint32_t e = en ? 1u : 0u;
    asm volatile(
        "{\n\t.reg .pred p;\n\tsetp.ne.u32 p, %4, 0;\n\t"
        "tcgen05.mma.cta_group::1.kind::f16 [%0], %1, %2, %3, {%5, %5, %5, %5}, p;\n\t}"
        :: "r"(d), "l"(ad), "l"(bd), "r"(IDESC_K4), "r"(e), "r"(0u) : "memory");
}
#endif  // K4_TC

// ---------------------------------------------------------------------------
// kc_conv: split fp32 rows into swizzled bf16 hi/lo tile blocks (once).
// grid 256, block 256. blocks 0-127: A (zw rows), 128-255: B (pred rows).
// block -> (tile 0..31 of 128 rows, K-phase 0..1, sub-half 0..1).
// ---------------------------------------------------------------------------
__global__ __launch_bounds__(256) void kc_conv(const float* __restrict__ zw0,
                                               const float* __restrict__ zw1)
{
    const int bp = blockIdx.x;
    const int isB = bp >> 7;
    const int r = bp & 127;
    const int x = r >> 1;              // (tile, phase) 0..63
    const int sub = r & 1;
    const int tile = x >> 1, p = x & 1;
    const int t = threadIdx.x;

    const float4* src;
    int rbase;
    unsigned char *dhi, *dlo;
    if (!isB) {
        src = (tile < 16) ? (const float4*)zw0 : (const float4*)zw1;
        rbase = (tile & 15) * 128;
        dhi = g_Ahi + (size_t)x * 16384;
        dlo = g_Alo + (size_t)x * 16384;
    } else {
        src = (const float4*)g_pred;
        rbase = tile * 128;
        dhi = g_Bhi + (size_t)x * 16384;
        dlo = g_Blo + (size_t)x * 16384;
    }
#pragma unroll
    for (int i = 0; i < 4; i++) {
        int c = sub * 1024 + t + 256 * i;   // 0..2047
        int lr = c >> 4, kq = c & 15;
        float4 v = __ldg(src + (size_t)(rbase + lr) * 32 + p * 16 + kq);
        uint2 hi, lo; cvt4(v, hi, lo);
        uint32_t off = swz((uint32_t)(lr * 128 + kq * 8));
        *(uint2*)(dhi + off) = hi;
        *(uint2*)(dlo + off) = lo;
    }
}

// ---------------------------------------------------------------------------
// K1: zt = relu(zw @ lw.T + lb); s = tanh(zt@a1.T+a1b)@a2 + a2b
// grid (64, 2), block 256.
// ---------------------------------------------------------------------------
__global__ __launch_bounds__(256) void k1_zt_s(
    const float* __restrict__ zw0, const float* __restrict__ zw1,
    const float* __restrict__ l0w, const float* __restrict__ l0b,
    const float* __restrict__ l1w, const float* __restrict__ l1b,
    const float* __restrict__ a01w, const float* __restrict__ a01b,
    const float* __restrict__ a02w, const float* __restrict__ a02b,
    const float* __restrict__ a11w, const float* __restrict__ a11b,
    const float* __restrict__ a12w, const float* __restrict__ a12b)
{
    __shared__ float sLW[64 * 132];
    __shared__ float sZT[32 * 65];
    __shared__ float sA1T[64 * 33];

    const int g = blockIdx.y;
    const float* zw  = g ? zw1  : zw0;
    const float* lw  = g ? l1w  : l0w;
    const float* lb  = g ? l1b  : l0b;
    const float* a1w = g ? a11w : a01w;
    const float* a1b = g ? a11b : a01b;
    const float* a2w = g ? a12w : a02w;
    const float* a2b = g ? a12b : a02b;

    const int t = threadIdx.x;
    const int r0 = blockIdx.x * 32;

    {
        const float4* src = (const float4*)lw;
#pragma unroll
        for (int i = 0; i < 8; i++) {
            int idx = t + 256 * i;
            int o = idx >> 5, q = idx & 31;
            *(float4*)&sLW[o * 132 + q * 4] = __ldg(src + idx);
        }
    }
    for (int i = t; i < 2048; i += 256) {
        int o = i >> 6, k = i & 63;
        sA1T[k * 33 + o] = __ldg(a1w + i);
    }
    __syncthreads();

    const int r = t >> 3, cg = t & 7;
    float acc[8];
#pragma unroll
    for (int i = 0; i < 8; i++) acc[i] = __ldg(lb + cg + 8 * i);

    const float4* zp = (const float4*)(zw + (size_t)(r0 + r) * 128);
#pragma unroll 8
    for (int q = 0; q < 32; q++) {
        float4 a = __ldg(zp + q);
#pragma unroll
        for (int i = 0; i < 8; i++) {
            float4 w = *(const float4*)&sLW[(cg + 8 * i) * 132 + q * 4];
            acc[i] += a.x * w.x + a.y * w.y + a.z * w.z + a.w * w.w;
        }
    }
#pragma unroll
    for (int i = 0; i < 8; i++) {
        float v = fmaxf(acc[i], 0.0f);
        sZT[r * 65 + cg + 8 * i] = v;
        g_zt[(size_t)(g * BG + r0 + r) * 64 + cg + 8 * i] = v;
    }
    __syncthreads();

    const int w = t >> 5, lane = t & 31;
    const float a2v  = __ldg(a2w + lane);
    const float a1bv = __ldg(a1b + lane);
    const float a2bv = __ldg(a2b);
    for (int rr = 0; rr < 4; rr++) {
        const int row = w * 4 + rr;
        float d = a1bv;
#pragma unroll 8
        for (int k = 0; k < 64; k++)
            d += sZT[row * 65 + k] * sA1T[k * 33 + lane];
        float v = tanhf(d) * a2v;
#pragma unroll
        for (int off = 16; off; off >>= 1) v += __shfl_down_sync(0xffffffffu, v, off);
        if (lane == 0) g_s[g * BG + r0 + row] = v + a2bv;
    }
}

// ---------------------------------------------------------------------------
// K2b: per-chunk (128 rows) partials: m_c = max s; S_c = sum exp(s-m_c);
// T_c[k] = sum exp(s-m_c)*zt[:,k].  grid 32 (2 groups x 16 chunks), block 256.
// ---------------------------------------------------------------------------
__global__ __launch_bounds__(256) void k2b_chunk()
{
    __shared__ float red[128];
    __shared__ float sE[128];
    __shared__ float sP[4 * 64];

    const int b = blockIdx.x, t = threadIdx.x;
    const int g = b >> 4, ch = b & 15;
    const int row0 = ch * 128;

    if (t < 128) red[t] = g_s[g * BG + row0 + t];
    __syncthreads();
    for (int off = 64; off; off >>= 1) {
        if (t < off) red[t] = fmaxf(red[t], red[t + off]);
        __syncthreads();
    }
    const float mc = red[0];
    if (t == 0) g_mp[b] = mc;
    __syncthreads();
    if (t < 128) sE[t] = expf(g_s[g * BG + row0 + t] - mc);
    __syncthreads();

    const int c = t & 63, rg = t >> 6;    // 4 row-groups of 32
    float p = 0.0f;
#pragma unroll 4
    for (int j = 0; j < 32; j++) {
        int row = rg * 32 + j;
        p += sE[row] * g_zt[(size_t)(g * BG + row0 + row) * 64 + c];
    }
    sP[rg * 64 + c] = p;
    __syncthreads();

    if (t < 64)
        g_Tp[(size_t)b * 64 + t] = sP[t] + sP[64 + t] + sP[128 + t] + sP[192 + t];
    if (t == 64) {
        float S = 0.0f;
        for (int j = 0; j < 128; j++) S += sE[j];
        g_Sp2[b] = S;
    }
}

// ---------------------------------------------------------------------------
// K2c: combine 16 chunks per group -> g_m, g_Ssum, g_T. 1 block, 128 threads.
// ---------------------------------------------------------------------------
__global__ void k2c_combine()
{
    const int t = threadIdx.x;
    const int g = t >> 6, c = t & 63;
    float M = -1e30f;
#pragma unroll
    for (int ch = 0; ch < 16; ch++) M = fmaxf(M, g_mp[g * 16 + ch]);
    float T = 0.0f;
#pragma unroll
    for (int ch = 0; ch < 16; ch++)
        T += expf(g_mp[g * 16 + ch] - M) * g_Tp[(size_t)(g * 16 + ch) * 64 + c];
    g_T[g * 64 + c] = T;
    if (c == 0) {
        g_m[g] = M;
        float S = 0.0f;
#pragma unroll
        for (int ch = 0; ch < 16; ch++)
            S += expf(g_mp[g * 16 + ch] - M) * g_Sp2[g * 16 + ch];
        g_Ssum[g] = S;
    }
}

// ---------------------------------------------------------------------------
// K3: pred = pooled @ Ww.T + Wwb + c @ Wk.T + Wkb. grid 128, block 256.
// ---------------------------------------------------------------------------
__global__ __launch_bounds__(256) void k3_pred(
    const float* __restrict__ cin,
    const float* __restrict__ Wkw, const float* __restrict__ Wkb,
    const float* __restrict__ Ww0w, const float* __restrict__ Ww0b,
    const float* __restrict__ Ww1w, const float* __restrict__ Ww1b)
{
    __shared__ float sW[128 * 68];
    __shared__ float sU[32 * 68];
    __shared__ float sE[32], sI[32], sB[128];

    const int t = threadIdx.x;
    const int row0 = blockIdx.x * 32;
    const int g = row0 >= BG;
    const int lr0 = row0 - g * BG;
    const float* Www = g ? Ww1w : Ww0w;
    const float* Wwb = g ? Ww1b : Ww0b;

    if (t < 128) sB[t] = Wwb[t] + Wkb[t];
    if (t < 32) {
        float e = expf(g_s[g * BG + lr0 + t] - g_m[g]);
        sE[t] = e;
        sI[t] = 1.0f / (g_Ssum[g] - e);
    }
    {
        const float4* src = (const float4*)Www;
#pragma unroll
        for (int i = 0; i < 8; i++) {
            int idx = t + 256 * i;
            int o = idx >> 4, q = idx & 15;
            *(float4*)&sW[o * 68 + q * 4] = __ldg(src + idx);
        }
    }
    __syncthreads();
    for (int i = t; i < 32 * 64; i += 256) {
        int r = i >> 6, k = i & 63;
        sU[r * 68 + k] = (g_T[g * 64 + k] -
                          sE[r] * g_zt[(size_t)(g * BG + lr0 + r) * 64 + k]) * sI[r];
    }
    __syncthreads();

    const int r = t >> 3, cg = t & 7;
    float acc[16];
#pragma unroll
    for (int i = 0; i < 16; i++) acc[i] = sB[cg + 8 * i];
#pragma unroll 4
    for (int q = 0; q < 16; q++) {
        float4 a = *(const float4*)&sU[r * 68 + q * 4];
#pragma unroll
        for (int i = 0; i < 16; i++) {
            float4 w = *(const float4*)&sW[(cg + 8 * i) * 68 + q * 4];
            acc[i] += a.x * w.x + a.y * w.y + a.z * w.z + a.w * w.w;
        }
    }
    __syncthreads();

    {
        const float4* src = (const float4*)Wkw;
#pragma unroll
        for (int i = 0; i < 8; i++) {
            int idx = t + 256 * i;
            int o = idx >> 4, q = idx & 15;
            *(float4*)&sW[o * 68 + q * 4] = __ldg(src + idx);
        }
        const float4* cu = (const float4*)(cin + (size_t)row0 * 64);
#pragma unroll
        for (int i = 0; i < 2; i++) {
            int idx = t + 256 * i;
            int rr = idx >> 4, q = idx & 15;
            *(float4*)&sU[rr * 68 + q * 4] = __ldg(cu + idx);
        }
    }
    __syncthreads();
#pragma unroll 4
    for (int q = 0; q < 16; q++) {
        float4 a = *(const float4*)&sU[r * 68 + q * 4];
#pragma unroll
        for (int i = 0; i < 16; i++) {
            float4 w = *(const float4*)&sW[(cg + 8 * i) * 68 + q * 4];
            acc[i] += a.x * w.x + a.y * w.y + a.z * w.z + a.w * w.w;
        }
    }
#pragma unroll
    for (int i = 0; i < 16; i++)
        g_pred[(size_t)(row0 + r) * 128 + cg + 8 * i] = acc[i];
}

// ---------------------------------------------------------------------------
// K4: total = zw @ pred.T (128x256 tiles) + fused (max,sumexp) + diag.
// grid (16, 32), block 256. Round-10-proven copy/MMA machinery; B realized as
// two independent 128-col tiles, each with its own 1024-aligned descriptor.
// ---------------------------------------------------------------------------
#define K4_TILE 16384
#define K4_SMEM (6 * K4_TILE + 1024 + 64)

__global__ __launch_bounds__(256, 2) void k4_gemm(const float* __restrict__ zw0,
                                                  const float* __restrict__ zw1)
{
    extern __shared__ char dsm[];
    const int t = threadIdx.x;
    const int jt = blockIdx.x, it = blockIdx.y;
    const int row0 = it * 128;

#if K4_TC
    const uint32_t raw = smem_u32(dsm);
    const uint32_t sbase = (raw + 1023u) & ~1023u;
    const uint32_t AHI = sbase,              ALO = sbase + K4_TILE;
    const uint32_t B0H = sbase + 2 * K4_TILE, B0L = sbase + 3 * K4_TILE;
    const uint32_t B1H = sbase + 4 * K4_TILE, B1L = sbase + 5 * K4_TILE;
    const uint32_t hdr = sbase + 6 * K4_TILE;
    const uint32_t mbar = hdr + 8;
    const int wid = t >> 5, lid = t & 31;

    if (t == 0) MBAR_INIT(mbar, 1);
    if (wid == 0) { TC_ALLOC(hdr, 256); TC_RELINQ(); }
    __syncthreads();
    uint32_t tmem;
    asm volatile("ld.shared.b32 %0, [%1];" : "=r"(tmem) : "r"(hdr));

    uint4* sAh = (uint4*)(dsm + (AHI - raw));
    uint4* sAl = (uint4*)(dsm + (ALO - raw));
    uint4* s0h = (uint4*)(dsm + (B0H - raw));
    uint4* s0l = (uint4*)(dsm + (B0L - raw));
    uint4* s1h = (uint4*)(dsm + (B1H - raw));
    uint4* s1l = (uint4*)(dsm + (B1L - raw));

#pragma unroll 1
    for (int p = 0; p < 2; p++) {
        const uint4* gAh = (const uint4*)(g_Ahi + (size_t)(it * 2 + p) * K4_TILE);
        const uint4* gAl = (const uint4*)(g_Alo + (size_t)(it * 2 + p) * K4_TILE);
        const uint4* g0h = (const uint4*)(g_Bhi + (size_t)((jt * 2 + 0) * 2 + p) * K4_TILE);
        const uint4* g0l = (const uint4*)(g_Blo + (size_t)((jt * 2 + 0) * 2 + p) * K4_TILE);
        const uint4* g1h = (const uint4*)(g_Bhi + (size_t)((jt * 2 + 1) * 2 + p) * K4_TILE);
        const uint4* g1l = (const uint4*)(g_Blo + (size_t)((jt * 2 + 1) * 2 + p) * K4_TILE);

        uint4 rAh[4], rAl[4], r0h[4], r0l[4];
#pragma unroll
        for (int j = 0; j < 4; j++) {
            int idx = t + 256 * j;
            rAh[j] = __ldg(gAh + idx);
            rAl[j] = __ldg(gAl + idx);
            r0h[j] = __ldg(g0h + idx);
            r0l[j] = __ldg(g0l + idx);
        }
        if (p) MBAR_WAIT(mbar, 0);           // phase-0 MMAs done before reuse
#pragma unroll
        for (int j = 0; j < 4; j++) {
            int idx = t + 256 * j;
            sAh[idx] = rAh[j];
            sAl[idx] = rAl[j];
            s0h[idx] = r0h[j];
            s0l[idx] = r0l[j];
        }
        {
            uint4 r1h[4], r1l[4];
#pragma unroll
            for (int j = 0; j < 4; j++) {
                int idx = t + 256 * j;
                r1h[j] = __ldg(g1h + idx);
                r1l[j] = __ldg(g1l + idx);
            }
#pragma unroll
            for (int j = 0; j < 4; j++) {
                int idx = t + 256 * j;
                s1h[idx] = r1h[j];
                s1l[idx] = r1l[j];
            }
        }
        FENCE_ASYNC();
        __syncthreads();
        if (wid == 0 && elect_one()) {
            uint64_t dAh = make_desc(AHI), dAl = make_desc(ALO);
            uint64_t dBh[2] = { make_desc(B0H), make_desc(B1H) };
            uint64_t dBl[2] = { make_desc(B0L), make_desc(B1L) };
#pragma unroll
            for (int nh = 0; nh < 2; nh++) {
                uint32_t d = tmem + nh * 128;
#pragma unroll
                for (int ks = 0; ks < 4; ks++)
                    mma_ss(d, dAh + 2 * ks, dBh[nh] + 2 * ks, !(p == 0 && ks == 0));
#pragma unroll
                for (int ks = 0; ks < 4; ks++)
                    mma_ss(d, dAh + 2 * ks, dBl[nh] + 2 * ks, true);
#pragma unroll
                for (int ks = 0; ks < 4; ks++)
                    mma_ss(d, dAl + 2 * ks, dBh[nh] + 2 * ks, true);
            }
            TC_COMMIT(mbar);
        }
    }
    MBAR_WAIT(mbar, 1);
    TC_FENCE_AFTER();

    // epilogue: warp -> (subpartition sp rows, column half). 4 LDTM chunks each.
    const int sp = wid & 3, half = wid >> 2;
    const int lrow = sp * 32 + lid;
    const int gi = row0 + lrow;
    const bool dgt = (jt == (it >> 1)) && (half == (it & 1));
    float M = -1e30f, S = 0.0f;
    uint32_t rr[32];
#pragma unroll 1
    for (int ch = 0; ch < 4; ch++) {
        LDTM_X32(rr, tmem + half * 128 + ch * 32);
        TC_WAIT_LD();
        float cm = -1e30f;
#pragma unroll
        for (int j = 0; j < 32; j++) cm = fmaxf(cm, __uint_as_float(rr[j]));
        if (cm > M) { S *= __expf(M - cm); M = cm; }
        float ss = 0.0f;
#pragma unroll
        for (int j = 0; j < 32; j++) ss += __expf(__uint_as_float(rr[j]) - M);
        S += ss;
        if (dgt && (lrow >> 5) == ch) g_diag[gi] = __uint_as_float(rr[lrow & 31]);
    }
    float2* part = (float2*)dsm;             // [128][2], tiles free now
    part[lrow * 2 + half] = make_float2(M, S);
    __syncthreads();
    if (t < 128) {
        float2 p0 = part[t * 2 + 0], p1 = part[t * 2 + 1];
        float Mf, Sf;
        if (p0.x >= p1.x) { Mf = p0.x; Sf = p0.y + p1.y * __expf(p1.x - p0.x); }
        else              { Mf = p1.x; Sf = p1.y + p0.y * __expf(p0.x - p1.x); }
        g_pm[(size_t)(row0 + t) * 16 + jt] = Mf;
        g_ps[(size_t)(row0 + t) * 16 + jt] = Sf;
    }
    __syncthreads();
    if (t == 0) MBAR_INVAL(mbar);
    if (wid == 0) TC_DEALLOC(tmem, 256);
#else
    // ----------------- FFMA fallback (non-'a' pass): two 128-col halves ----
    float* smf = (float*)dsm;
    float* sA = smf;
    float* sB = smf + 32 * 132;
    const float* Ar = (row0 < BG) ? zw0 + (size_t)row0 * 128
                                  : zw1 + (size_t)(row0 - BG) * 128;
    const int ty = t >> 4, tx = t & 15;
    float Mh[2], Sh[2];

#pragma unroll 1
    for (int jh = 0; jh < 2; jh++) {
        const int col0 = jt * 256 + jh * 128;
        const float* Br = g_pred + (size_t)col0 * 128;
        float acc[8][8];
#pragma unroll
        for (int i = 0; i < 8; i++)
#pragma unroll
            for (int j = 0; j < 8; j++) acc[i][j] = 0.0f;

#pragma unroll 1
        for (int kt = 0; kt < 4; kt++) {
            __syncthreads();
#pragma unroll
            for (int i = 0; i < 4; i++) {
                int idx = t + 256 * i;
                int rr2 = idx >> 3;
                int kk = (idx & 7) << 2;
                float4 va = *(const float4*)(Ar + (size_t)rr2 * 128 + kt * 32 + kk);
                sA[(kk + 0) * 132 + rr2] = va.x;
                sA[(kk + 1) * 132 + rr2] = va.y;
                sA[(kk + 2) * 132 + rr2] = va.z;
                sA[(kk + 3) * 132 + rr2] = va.w;
                float4 vb = *(const float4*)(Br + (size_t)rr2 * 128 + kt * 32 + kk);
                sB[(kk + 0) * 132 + rr2] = vb.x;
                sB[(kk + 1) * 132 + rr2] = vb.y;
                sB[(kk + 2) * 132 + rr2] = vb.z;
                sB[(kk + 3) * 132 + rr2] = vb.w;
            }
            __syncthreads();
#pragma unroll 4
            for (int k = 0; k < 32; k++) {
                float4 a0 = *(const float4*)&sA[k * 132 + ty * 8];
                float4 a1 = *(const float4*)&sA[k * 132 + ty * 8 + 4];
                float4 b0 = *(const float4*)&sB[k * 132 + tx * 8];
                float4 b1 = *(const float4*)&sB[k * 132 + tx * 8 + 4];
                float av[8] = {a0.x, a0.y, a0.z, a0.w, a1.x, a1.y, a1.z, a1.w};
                float bv[8] = {b0.x, b0.y, b0.z, b0.w, b1.x, b1.y, b1.z, b1.w};
#pragma unroll
                for (int i = 0; i < 8; i++)
#pragma unroll
                    for (int j = 0; j < 8; j++) acc[i][j] += av[i] * bv[j];
            }
        }
        __syncthreads();

        if ((jt == (it >> 1)) && (jh == (it & 1)) && ty == tx) {
#pragma unroll
            for (int i = 0; i < 8; i++) g_diag[row0 + ty * 8 + i] = acc[i][i];
        }
        float2* red = (float2*)smf;
#pragma unroll
        for (int i = 0; i < 8; i++) {
            float mx = acc[i][0];
#pragma unroll
            for (int j = 1; j < 8; j++) mx = fmaxf(mx, acc[i][j]);
            float ss = 0.0f;
#pragma unroll
            for (int j = 0; j < 8; j++) ss += expf(acc[i][j] - mx);
            red[(ty * 8 + i) * 16 + tx] = make_float2(mx, ss);
        }
        __syncthreads();
        if (t < 128) {
            float M = -1e30f, S = 0.0f;
#pragma unroll
            for (int p = 0; p < 16; p++) {
                float2 v = red[t * 16 + p];
                if (v.x > M) { S = S * expf(M - v.x) + v.y; M = v.x; }
                else         { S += v.y * expf(v.x - M); }
            }
            Mh[jh] = M; Sh[jh] = S;
        }
        __syncthreads();
    }
    if (t < 128) {
        float Mf, Sf;
        if (Mh[0] >= Mh[1]) { Mf = Mh[0]; Sf = Sh[0] + Sh[1] * expf(Mh[1] - Mh[0]); }
        else                { Mf = Mh[1]; Sf = Sh[1] + Sh[0] * expf(Mh[0] - Mh[1]); }
        g_pm[(size_t)(row0 + t) * 16 + jt] = Mf;
        g_ps[(size_t)(row0 + t) * 16 + jt] = Sf;
    }
#endif
}

// ---------------------------------------------------------------------------
// K5a: per-128-row partial of sum(lse - diag). grid 32, block 128.
// ---------------------------------------------------------------------------
__global__ void k5a_partial()
{
    __shared__ float red[128];
    const int b = blockIdx.x, t = threadIdx.x;
    const int row = b * 128 + t;
    float M = -1e30f, S = 0.0f;
#pragma unroll 4
    for (int p = 0; p < 16; p++) {
        float m = g_pm[(size_t)row * 16 + p];
        float s = g_ps[(size_t)row * 16 + p];
        if (m > M) { S = S * expf(M - m) + s; M = m; }
        else       { S += s * expf(m - M); }
    }
    red[t] = (M + logf(S)) - g_diag[row];
    __syncthreads();
    for (int off = 64; off; off >>= 1) {
        if (t < off) red[t] += red[t + off];
        __syncthreads();
    }
    if (t == 0) g_part[b] = red[0];
}

__global__ void k5b_final(float* __restrict__ out)
{
    if (threadIdx.x == 0) {
        float a = 0.0f;
#pragma unroll
        for (int i = 0; i < 32; i++) a += g_part[i];
        out[0] = a / (float)BT;
    }
}

// ---------------------------------------------------------------------------
extern "C" void kernel_launch(void* const* d_in, const int* in_sizes, int n_in,
                              void* d_out, int out_size)
{
    const float* zw0  = (const float*)d_in[0];
    const float* zw1  = (const float*)d_in[1];
    const float* cin  = (const float*)d_in[2];
    const float* Wkw  = (const float*)d_in[3];
    const float* Wkb  = (const float*)d_in[4];
    const float* Ww0w = (const float*)d_in[5];
    const float* Ww0b = (const float*)d_in[6];
    const float* Ww1w = (const float*)d_in[7];
    const float* Ww1b = (const float*)d_in[8];
    const float* l0w  = (const float*)d_in[9];
    const float* l0b  = (const float*)d_in[10];
    const float* l1w  = (const float*)d_in[11];
    const float* l1b  = (const float*)d_in[12];
    const float* a01w = (const float*)d_in[13];
    const float* a01b = (const float*)d_in[14];
    const float* a02w = (const float*)d_in[15];
    const float* a02b = (const float*)d_in[16];
    const float* a11w = (const float*)d_in[17];
    const float* a11b = (const float*)d_in[18];
    const float* a12w = (const float*)d_in[19];
    const float* a12b = (const float*)d_in[20];

    cudaFuncSetAttribute(k4_gemm, cudaFuncAttributeMaxDynamicSharedMemorySize, K4_SMEM);

    k1_zt_s<<<dim3(64, 2), 256>>>(zw0, zw1, l0w, l0b, l1w, l1b,
                                  a01w, a01b, a02w, a02b,
                                  a11w, a11b, a12w, a12b);
    k2b_chunk<<<32, 256>>>();
    k2c_combine<<<1, 128>>>();
    k3_pred<<<128, 256>>>(cin, Wkw, Wkb, Ww0w, Ww0b, Ww1w, Ww1b);
    kc_conv<<<256, 256>>>(zw0, zw1);
    k4_gemm<<<dim3(16, 32), 256, K4_SMEM>>>(zw0, zw1);
    k5a_partial<<<32, 128>>>();
    k5b_final<<<1, 32>>>((float*)d_out);
}